// round 13
// baseline (speedup 1.0000x reference)
#include <cuda_runtime.h>
#include <cuda_fp16.h>
#include <math.h>
#include <stdint.h>

typedef __half hf;

// ---------------- problem constants ----------------
#define Bb 4
#define NTOK 5440
#define Mrows (Bb * NTOK)   // 21760
#define Dd 256
#define FFd 1024
#define NHh 8
#define NLl 4
#define NPp 4
#define DHh 32
#define GPERS 304

__device__ __constant__ int c_lvl_W[4]     = {64, 32, 16, 8};
__device__ __constant__ int c_lvl_start[4] = {0, 4096, 5120, 5376};

// ---------------- scratch (device globals) ----------------
__device__ hf    g_srcf[Mrows * Dd];
__device__ hf    g_qf  [Mrows * Dd];
__device__ hf    g_af  [Mrows * Dd];
__device__ hf    g_xf  [Mrows * Dd];
__device__ hf    g_hf  [Mrows * FFd];
__device__ hf    g_valhf[Mrows * Dd];          // value fp16 row-major (sampler)
__device__ float g_off  [Mrows * Dd];          // offsets; later reused as ffn2 partial 0
__device__ float g_attn [Mrows * 128];
__device__ float g_t1   [Mrows * Dd];          // pre-LN1; later reused as ffn2 partial 1
__device__ float g_x    [Mrows * Dd];
__device__ float g_t2   [Mrows * Dd];          // x + b2 (seeded by LN1)
// fp16 weights, blocked layout
__device__ hf g_wv[Dd*Dd];
__device__ hf g_wc[384*Dd];
__device__ hf g_wo[Dd*Dd];
__device__ hf g_w1[FFd*Dd];
__device__ hf g_w2[Dd*FFd];

// ---------------- blocked layout ----------------
__device__ __forceinline__ size_t blk_off(int row, int k, int K) {
    uint32_t o = (uint32_t)(row & 127) * 64 + (uint32_t)(k & 31) * 2;
    o = o ^ ((o >> 3) & 0x70);
    return ((size_t)((row >> 7) * (K >> 5) + (k >> 5)) << 13) + o;
}
#define SWZ(o) ((o) ^ (((o) >> 3) & 0x70))

// ---------------- PTX helpers ----------------
__device__ __forceinline__ uint32_t smem_u32(const void* p) {
    uint32_t a;
    asm("{ .reg .u64 t; cvta.to.shared.u64 t, %1; cvt.u32.u64 %0, t; }" : "=r"(a) : "l"(p));
    return a;
}
#define MBAR_INIT(addr, cnt) \
    asm volatile("mbarrier.init.shared.b64 [%0], %1;" :: "r"((uint32_t)(addr)), "r"((uint32_t)(cnt)) : "memory")
#define MBAR_ARRIVE(addr) \
    asm volatile("mbarrier.arrive.shared.b64 _, [%0];" :: "r"((uint32_t)(addr)) : "memory")
#define MBAR_EXPECT_TX(addr, tx) \
    asm volatile("mbarrier.arrive.expect_tx.shared.b64 _, [%0], %1;" :: "r"((uint32_t)(addr)), "r"((uint32_t)(tx)) : "memory")
#define BULK_G2S(dst, src, bytes, mbar) \
    asm volatile("cp.async.bulk.shared::cluster.global.mbarrier::complete_tx::bytes [%0], [%1], %2, [%3];" \
        :: "r"((uint32_t)(dst)), "l"(src), "r"((uint32_t)(bytes)), "r"((uint32_t)(mbar)) : "memory")
#define FENCE_ASYNC() asm volatile("fence.proxy.async.shared::cta;" ::: "memory")

#define MBAR_WAIT(addr, par) do { \
    uint32_t _m = (uint32_t)(addr); uint32_t _p = (uint32_t)(par); uint32_t _d; \
    asm volatile("{\n\t.reg .pred p;\n\t" \
        "mbarrier.try_wait.parity.acquire.cta.shared::cta.b64 p, [%1], %2;\n\t" \
        "selp.b32 %0, 1, 0, p;\n\t}" : "=r"(_d) : "r"(_m), "r"(_p) : "memory"); \
    if (!_d) { \
        asm volatile("{\n\t.reg .pred P1;\n\t" \
            "WL_%=:\n\t" \
            "mbarrier.try_wait.parity.acquire.cta.shared::cta.b64 P1, [%0], %1, 0x989680;\n\t" \
            "@P1 bra.uni WD_%=;\n\t" \
            "bra.uni WL_%=;\n\t" \
            "WD_%=:\n\t}" :: "r"(_m), "r"(_p) : "memory"); \
    } } while (0)

__device__ __forceinline__ void ldsm4(uint32_t* r, uint32_t a) {
    asm volatile("ldmatrix.sync.aligned.m8n8.x4.shared.b16 {%0,%1,%2,%3}, [%4];"
        : "=r"(r[0]), "=r"(r[1]), "=r"(r[2]), "=r"(r[3]) : "r"(a));
}
__device__ __forceinline__ void mma16816(float* d, const uint32_t* a, const uint32_t* b) {
    asm volatile("mma.sync.aligned.m16n8k16.row.col.f32.f16.f16.f32 "
        "{%0,%1,%2,%3}, {%4,%5,%6,%7}, {%8,%9}, {%0,%1,%2,%3};"
        : "+f"(d[0]), "+f"(d[1]), "+f"(d[2]), "+f"(d[3])
        : "r"(a[0]), "r"(a[1]), "r"(a[2]), "r"(a[3]), "r"(b[0]), "r"(b[1]));
}

__device__ __forceinline__ uint2 conv4(float4 v) {
    __half2 a = __floats2half2_rn(v.x, v.y);
    __half2 b = __floats2half2_rn(v.z, v.w);
    uint2 r; r.x = *(uint32_t*)&a; r.y = *(uint32_t*)&b;
    return r;
}

// ---------------- prep kernels ----------------
__global__ void src_q_conv(const float* __restrict__ src, const float* __restrict__ pos,
                           hf* __restrict__ sf, hf* __restrict__ qf) {
    int i = blockIdx.x * blockDim.x + threadIdx.x;
    int e = i * 4;
    int m = e >> 8, k = e & 255;
    size_t off = blk_off(m, k, 256);
    float4 s = ((const float4*)src)[i];
    float4 p = ((const float4*)pos)[i];
    *(uint2*)((char*)sf + off) = conv4(s);
    float4 q = make_float4(s.x + p.x, s.y + p.y, s.z + p.z, s.w + p.w);
    *(uint2*)((char*)qf + off) = conv4(q);
}

struct WConvArgs {
    const float* s[6];
    hf* h[6];
    int n4[6];
    int kshift[6];
    int rowoff[6];
};
__global__ void wconv_all(WConvArgs a) {
    int seg = blockIdx.y;
    int i = blockIdx.x * blockDim.x + threadIdx.x;
    if (i >= a.n4[seg]) return;
    int ks = a.kshift[seg];
    int K = 1 << ks;
    int e = i * 4;
    int m = (e >> ks) + a.rowoff[seg];
    int k = e & (K - 1);
    size_t off = blk_off(m, k, K);
    *(uint2*)((char*)a.h[seg] + off) = conv4(((const float4*)a.s[seg])[i]);
}

// ---------------- persistent bulk-copy HMMA GEMM ----------------
// 512 threads (16 warps, 4x4 warp grid, 32x32 warp tile), NT=128,
// 64-k super-chunks (2x 8KB blocks per operand), 3-stage bulk pipeline.
#define NST 3
#define STG_B 32768           // 16KB A + 16KB B per super-chunk
#define SMEM_GEMM (128 + NST * STG_B)
enum { E_MASK_F16 = 0, E_OFFATTN = 1, E_ADD = 2, E_RELU_F16 = 3, E_PART = 4 };

template <int EPI>
__global__ __launch_bounds__(512, 2)
void tc_gemm(const hf* __restrict__ A, const hf* __restrict__ B,
             const float* __restrict__ bias, const float* __restrict__ bias2,
             float* __restrict__ outF, float* __restrict__ outF2,
             hf* __restrict__ oF16,
             int NJ, int NTC, int KTC, int CHUNKS, int KCA, int N,
             const float* __restrict__ add, const unsigned char* __restrict__ mask) {
    extern __shared__ char sm[];
    const uint32_t smb = smem_u32(sm);
    const uint32_t fullb = smb, emptyb = smb + 48;
    const uint32_t stg0 = smb + 128;

    const int tid = threadIdx.x;
    const int wid = tid >> 5, lane = tid & 31;
    const int wm = wid & 3, wn = wid >> 2;     // 4x4 warp grid, 32x32 tiles
    const int g = lane >> 2, t4 = lane & 3;

    if (tid == 0) {
#pragma unroll
        for (int s = 0; s < NST; s++) {
            MBAR_INIT(fullb + s * 16, 1);
            MBAR_INIT(emptyb + s * 16, 16);
        }
        FENCE_ASYNC();
    }
    __syncthreads();

    const int G = gridDim.x;
    const int bid = blockIdx.x;
    const int njm = (bid < NJ) ? ((NJ - bid + G - 1) / G) : 0;
    const int T = njm * CHUNKS;

    auto issue = [&](int t) {
        int jl = t / CHUNKS, c = t - jl * CHUNKS;
        int job = bid + jl * G;
        int n = job % NTC;
        int r = job / NTC;
        int kt = (KTC == 2) ? (r & 1) : 0;
        int m = (KTC == 2) ? (r >> 1) : r;
        int cg = kt * CHUNKS + c;
        int s = t % NST;
        uint32_t dst = stg0 + s * STG_B;
        uint32_t mb = fullb + s * 16;
        MBAR_EXPECT_TX(mb, STG_B);
        const char* a0 = (const char*)A + (((size_t)m * KCA + cg * 2) << 13);
        const char* b0 = (const char*)B + (((size_t)n * KCA + cg * 2) << 13);
        BULK_G2S(dst,         a0, 16384, mb);
        BULK_G2S(dst + 16384, b0, 16384, mb);
    };

    if (tid == 0) {
        int pre = T < NST ? T : NST;
        for (int t = 0; t < pre; t++) issue(t);
    }

    float acc[2][4][4];
#pragma unroll
    for (int i = 0; i < 2; i++)
#pragma unroll
        for (int j = 0; j < 4; j++)
#pragma unroll
            for (int r = 0; r < 4; r++) acc[i][j][r] = 0.f;

    const uint32_t rA = (uint32_t)(lane & 15);
    const uint32_t qA = (uint32_t)(lane >> 4) * 16;
    const uint32_t rB = (uint32_t)(((lane >> 4) & 1) * 8 + (lane & 7));
    const uint32_t qB = (uint32_t)((lane >> 3) & 1) * 16;

    int bm = 0, bn = 0, ktile = 0;

    for (int t = 0; t < T; t++) {
        int jl = t / CHUNKS, c = t - jl * CHUNKS;
        if (c == 0) {
            int job = bid + jl * G;
            int n = job % NTC;
            int r = job / NTC;
            ktile = (KTC == 2) ? (r & 1) : 0;
            int m = (KTC == 2) ? (r >> 1) : r;
            bm = m * 128;
            bn = n * 128;
        }
        const int s = t % NST;
        const int u = t / NST;
        MBAR_WAIT(fullb + s * 16, u & 1);

        const uint32_t st = stg0 + s * STG_B;
#pragma unroll
        for (int ks = 0; ks < 4; ks++) {
            const uint32_t blk = (uint32_t)(ks >> 1) * 8192;
            const uint32_t kb = (uint32_t)(ks & 1) * 32;
            uint32_t Af[2][4], Bf[2][4];
#pragma unroll
            for (int i = 0; i < 2; i++) {
                uint32_t o = (wm * 32 + i * 16 + rA) * 64 + qA + kb;
                o = SWZ(o);
                ldsm4(Af[i], st + blk + o);
            }
#pragma unroll
            for (int p = 0; p < 2; p++) {
                uint32_t o = (wn * 32 + p * 16 + rB) * 64 + qB + kb;
                o = SWZ(o);
                ldsm4(Bf[p], st + 16384 + blk + o);
            }
#pragma unroll
            for (int i = 0; i < 2; i++)
#pragma unroll
                for (int j = 0; j < 4; j++) {
                    const uint32_t* bp = &Bf[j >> 1][(j & 1) * 2];
                    mma16816(acc[i][j], Af[i], bp);
                }
        }
        __syncwarp();
        if (lane == 0) MBAR_ARRIVE(emptyb + s * 16);
        if (tid == 0 && t + NST < T) {
            MBAR_WAIT(emptyb + s * 16, u & 1);
            issue(t + NST);
        }

        if (c == CHUNKS - 1) {
#pragma unroll
            for (int i = 0; i < 2; i++) {
                int row0 = bm + wm * 32 + i * 16 + g;
#pragma unroll
                for (int j = 0; j < 4; j++) {
                    int col = bn + wn * 32 + j * 8 + 2 * t4;
                    float b0, b1;
                    if (EPI == E_PART) { b0 = 0.f; b1 = 0.f; }
                    else if (EPI == E_OFFATTN && bn == 256) {
                        b0 = bias2[col - 256]; b1 = bias2[col - 255];
                    } else {
                        b0 = bias[col]; b1 = bias[col + 1];
                    }
#pragma unroll
                    for (int half = 0; half < 2; half++) {
                        int row = row0 + half * 8;
                        float v0 = acc[i][j][half * 2 + 0] + b0;
                        float v1 = acc[i][j][half * 2 + 1] + b1;
                        if (EPI == E_MASK_F16) {
                            if (mask[row]) { v0 = 0.f; v1 = 0.f; }
                            __half2 pk = __floats2half2_rn(v0, v1);
                            *(uint32_t*)(oF16 + (size_t)row * N + col) = *(uint32_t*)&pk;
                        } else if (EPI == E_OFFATTN) {
                            if (bn == 256)
                                *(float2*)(outF2 + (size_t)row * 128 + (col - 256)) = make_float2(v0, v1);
                            else
                                *(float2*)(outF + (size_t)row * 256 + col) = make_float2(v0, v1);
                        } else if (EPI == E_ADD) {
                            float2 r2 = *(const float2*)(add + (size_t)row * N + col);
                            *(float2*)(outF + (size_t)row * N + col) = make_float2(v0 + r2.x, v1 + r2.y);
                        } else if (EPI == E_RELU_F16) {
                            v0 = fmaxf(v0, 0.f); v1 = fmaxf(v1, 0.f);
                            __half2 pk = __floats2half2_rn(v0, v1);
                            size_t off = blk_off(row, col, N);
                            *(uint32_t*)((char*)oF16 + off) = *(uint32_t*)&pk;
                        } else if (EPI == E_PART) {
                            float* base = ktile ? outF2 : outF;
                            *(float2*)(base + (size_t)row * N + col) = make_float2(v0, v1);
                        }
                    }
                }
            }
#pragma unroll
            for (int i = 0; i < 2; i++)
#pragma unroll
                for (int j = 0; j < 4; j++)
#pragma unroll
                    for (int r = 0; r < 4; r++) acc[i][j][r] = 0.f;
        }
    }
}

// ---------------- msdeform sampling (fp16 value) ----------------
__global__ __launch_bounds__(1024)
void sample_kernel(const float* __restrict__ ref, hf* __restrict__ af) {
    __shared__ int   s_off[32][32][4];
    __shared__ float s_w  [32][32][4];

    const int wid = threadIdx.x >> 5, lane = threadIdx.x & 31;
    const int tw = wid & 3;
    const int m = blockIdx.x * 8 + (wid >> 2);
    const int b = m / NTOK;
    const int hh = lane >> 4;
    const int head = (tw << 1) | hh;
    const int pt = lane & 15;

    float logit = g_attn[(size_t)m * 128 + head * 16 + pt];
    float mx = logit;
#pragma unroll
    for (int o = 8; o; o >>= 1) mx = fmaxf(mx, __shfl_xor_sync(0xffffffffu, mx, o, 16));
    float e = __expf(logit - mx);
    float sum = e;
#pragma unroll
    for (int o = 8; o; o >>= 1) sum += __shfl_xor_sync(0xffffffffu, sum, o, 16);
    float aw = e / sum;

    const int l = pt >> 2;
    const int Wl = c_lvl_W[l];
    float2 oxy = ((const float2*)g_off)[(size_t)m * 128 + head * 16 + pt];
    float2 rxy = ((const float2*)ref)[(size_t)m * 4 + l];
    float x = fmaf(rxy.x, (float)Wl, oxy.x) - 0.5f;
    float y = fmaf(rxy.y, (float)Wl, oxy.y) - 0.5f;
    float x0f = floorf(x), y0f = floorf(y);
    float fx = x - x0f, fy = y - y0f;
    int x0 = (int)x0f, y0 = (int)y0f;
    int x1 = x0 + 1, y1 = y0 + 1;
    bool vx0 = (x0 >= 0) & (x0 < Wl);
    bool vx1 = (x1 >= 0) & (x1 < Wl);
    bool vy0 = (y0 >= 0) & (y0 < Wl);
    bool vy1 = (y1 >= 0) & (y1 < Wl);
    int xc0 = min(max(x0, 0), Wl - 1), xc1 = min(max(x1, 0), Wl - 1);
    int yc0 = min(max(y0, 0), Wl - 1), yc1 = min(max(y1, 0), Wl - 1);
    float w00 = (vx0 & vy0) ? aw * (1.f - fx) * (1.f - fy) : 0.f;
    float w10 = (vx1 & vy0) ? aw * fx * (1.f - fy) : 0.f;
    float w01 = (vx0 & vy1) ? aw * (1.f - fx) * fy : 0.f;
    float w11 = (vx1 & vy1) ? aw * fx * fy : 0.f;
    int rowbase = b * NTOK + c_lvl_start[l];
    int hb = head * 64;
    s_off[wid][lane][0] = (rowbase + yc0 * Wl + xc0) * 512 + hb;
    s_off[wid][lane][1] = (rowbase + yc0 * Wl + xc1) * 512 + hb;
    s_off[wid][lane][2] = (rowbase + yc1 * Wl + xc0) * 512 + hb;
    s_off[wid][lane][3] = (rowbase + yc1 * Wl + xc1) * 512 + hb;
    s_w[wid][lane][0] = w00; s_w[wid][lane][1] = w10;
    s_w[wid][lane][2] = w01; s_w[wid][lane][3] = w11;
    __syncwarp();

    const int c2 = lane & 15;
    float accx = 0.f, accy = 0.f;
    const char* vb = (const char*)g_valhf + c2 * 4;
#pragma unroll
    for (int s = 0; s < 16; s++) {
        int slot = (hh << 4) | s;
        int4 io = *(const int4*)s_off[wid][slot];
        float4 wv = *(const float4*)s_w[wid][slot];
        __half2 v;
        float2 vf;
        v = *(const __half2*)(vb + io.x); vf = __half22float2(v);
        accx = fmaf(wv.x, vf.x, accx); accy = fmaf(wv.x, vf.y, accy);
        v = *(const __half2*)(vb + io.y); vf = __half22float2(v);
        accx = fmaf(wv.y, vf.x, accx); accy = fmaf(wv.y, vf.y, accy);
        v = *(const __half2*)(vb + io.z); vf = __half22float2(v);
        accx = fmaf(wv.z, vf.x, accx); accy = fmaf(wv.z, vf.y, accy);
        v = *(const __half2*)(vb + io.w); vf = __half22float2(v);
        accx = fmaf(wv.w, vf.x, accx); accy = fmaf(wv.w, vf.y, accy);
    }

    __half2 pk = __floats2half2_rn(accx, accy);
    int k0 = head * 32 + c2 * 2;
    size_t off = blk_off(m, k0, 256);
    *(uint32_t*)((char*)af + off) = *(uint32_t*)&pk;
}

// ---------------- LayerNorm over D=256 ----------------
template <int MODE>
__global__ void ln_kernel(const float* __restrict__ in, const float* __restrict__ g,
                          const float* __restrict__ be, float* __restrict__ out,
                          hf* __restrict__ oh,
                          float* __restrict__ t2i, const float* __restrict__ b2,
                          const float* __restrict__ p0, const float* __restrict__ p1) {
    int m = blockIdx.x;
    int t = threadIdx.x;
    float v = in[(size_t)m * Dd + t];
    if (MODE == 2) v += p0[(size_t)m * Dd + t] + p1[(size_t)m * Dd + t];
    float s = v, sq = v * v;
#pragma unroll
    for (int o = 16; o; o >>= 1) {
        s += __shfl_xor_sync(0xffffffffu, s, o);
        sq += __shfl_xor_sync(0xffffffffu, sq, o);
    }
    __shared__ float ss[8], ssq[8];
    __shared__ float s_mean, s_rstd;
    if ((t & 31) == 0) { ss[t >> 5] = s; ssq[t >> 5] = sq; }
    __syncthreads();
    if (t == 0) {
        float ts = 0.f, tsq = 0.f;
#pragma unroll
        for (int i = 0; i < 8; i++) { ts += ss[i]; tsq += ssq[i]; }
        float mean = ts * (1.f / Dd);
        float var = tsq * (1.f / Dd) - mean * mean;
        s_mean = mean;
        s_rstd = rsqrtf(var + 1e-5f);
    }
    __syncthreads();
    float o = (v - s_mean) * s_rstd * g[t] + be[t];
    out[(size_t)m * Dd + t] = o;
    if (MODE == 1) {
        size_t off = blk_off(m, t, 256);
        *(hf*)((char*)oh + off) = __float2half_rn(o);
        t2i[(size_t)m * Dd + t] = o + b2[t];
    }
}

// ---------------- launch ----------------
extern "C" void kernel_launch(void* const* d_in, const int* in_sizes, int n_in,
                              void* d_out, int out_size) {
    const float* src   = (const float*)d_in[0];
    const float* pos   = (const float*)d_in[1];
    const float* ref   = (const float*)d_in[2];
    const float* w_val = (const float*)d_in[3];
    const float* b_val = (const float*)d_in[4];
    const float* w_off = (const float*)d_in[5];
    const float* b_off = (const float*)d_in[6];
    const float* w_att = (const float*)d_in[7];
    const float* b_att = (const float*)d_in[8];
    const float* w_out = (const float*)d_in[9];
    const float* b_out = (const float*)d_in[10];
    const float* g1    = (const float*)d_in[11];
    const float* be1   = (const float*)d_in[12];
    const float* w1    = (const float*)d_in[13];
    const float* b1    = (const float*)d_in[14];
    const float* w2    = (const float*)d_in[15];
    const float* b2    = (const float*)d_in[16];
    const float* g2    = (const float*)d_in[17];
    const float* be2   = (const float*)d_in[18];
    const unsigned char* mask = (const unsigned char*)d_in[21];

    hf *srcf, *qf, *af, *xf, *hff, *valhf;
    hf *wv, *wc, *wo, *w1p, *w2p;
    float *p_off, *p_attn, *p_t1, *p_x, *p_t2;
    cudaGetSymbolAddress((void**)&srcf, g_srcf);
    cudaGetSymbolAddress((void**)&qf, g_qf);
    cudaGetSymbolAddress((void**)&af, g_af);
    cudaGetSymbolAddress((void**)&xf, g_xf);
    cudaGetSymbolAddress((void**)&hff, g_hf);
    cudaGetSymbolAddress((void**)&valhf, g_valhf);
    cudaGetSymbolAddress((void**)&wv, g_wv);
    cudaGetSymbolAddress((void**)&wc, g_wc);
    cudaGetSymbolAddress((void**)&wo, g_wo);
    cudaGetSymbolAddress((void**)&w1p, g_w1);
    cudaGetSymbolAddress((void**)&w2p, g_w2);
    cudaGetSymbolAddress((void**)&p_off, g_off);
    cudaGetSymbolAddress((void**)&p_attn, g_attn);
    cudaGetSymbolAddress((void**)&p_t1, g_t1);
    cudaGetSymbolAddress((void**)&p_x, g_x);
    cudaGetSymbolAddress((void**)&p_t2, g_t2);

    const int M = Mrows;
    cudaFuncSetAttribute(tc_gemm<E_MASK_F16>, cudaFuncAttributeMaxDynamicSharedMemorySize, SMEM_GEMM);
    cudaFuncSetAttribute(tc_gemm<E_OFFATTN>,  cudaFuncAttributeMaxDynamicSharedMemorySize, SMEM_GEMM);
    cudaFuncSetAttribute(tc_gemm<E_ADD>,      cudaFuncAttributeMaxDynamicSharedMemorySize, SMEM_GEMM);
    cudaFuncSetAttribute(tc_gemm<E_RELU_F16>, cudaFuncAttributeMaxDynamicSharedMemorySize, SMEM_GEMM);
    cudaFuncSetAttribute(tc_gemm<E_PART>,     cudaFuncAttributeMaxDynamicSharedMemorySize, SMEM_GEMM);

    // prep
    src_q_conv<<<(M * Dd / 4) / 256, 256>>>(src, pos, srcf, qf);
    WConvArgs wa;
    wa.s[0] = w_val; wa.h[0] = wv;  wa.n4[0] = Dd * Dd / 4;  wa.kshift[0] = 8;  wa.rowoff[0] = 0;
    wa.s[1] = w_off; wa.h[1] = wc;  wa.n4[1] = Dd * Dd / 4;  wa.kshift[1] = 8;  wa.rowoff[1] = 0;
    wa.s[2] = w_att; wa.h[2] = wc;  wa.n4[2] = 128 * Dd / 4; wa.kshift[2] = 8;  wa.rowoff[2] = 256;
    wa.s[3] = w_out; wa.h[3] = wo;  wa.n4[3] = Dd * Dd / 4;  wa.kshift[3] = 8;  wa.rowoff[3] = 0;
    wa.s[4] = w1;    wa.h[4] = w1p; wa.n4[4] = FFd * Dd / 4; wa.kshift[4] = 8;  wa.rowoff[4] = 0;
    wa.s[5] = w2;    wa.h[5] = w2p; wa.n4[5] = Dd * FFd / 4; wa.kshift[5] = 10; wa.rowoff[5] = 0;
    wconv_all<<<dim3(256, 6), 256>>>(wa);

    // value = mask(src @ Wv^T + b) -> fp16.  jobs: 170m x 2n, 4 super-chunks
    tc_gemm<E_MASK_F16><<<GPERS, 512, SMEM_GEMM>>>(
        srcf, wv, b_val, nullptr, nullptr, nullptr, valhf,
        340, 2, 1, 4, 8, Dd, nullptr, mask);
    // [off ; attn] = q @ Wc^T + b.  jobs: 170m x 3n
    tc_gemm<E_OFFATTN><<<GPERS, 512, SMEM_GEMM>>>(
        qf, wc, b_off, b_att, p_off, p_attn, nullptr,
        510, 3, 1, 4, 8, 384, nullptr, nullptr);
    // msdeform -> blocked fp16 a   (8 tokens per 1024-thr block)
    sample_kernel<<<M / 8, 1024>>>(ref, af);
    // t1 = src + a @ Wo^T + b.  jobs: 170m x 2n
    tc_gemm<E_ADD><<<GPERS, 512, SMEM_GEMM>>>(
        af, wo, b_out, nullptr, p_t1, nullptr, nullptr,
        340, 2, 1, 4, 8, Dd, src, nullptr);
    // x = LN(t1); t2init = x + b2
    ln_kernel<1><<<M, 256>>>(p_t1, g1, be1, p_x, xf, p_t2, b2, nullptr, nullptr);
    // h = relu(x @ W1^T + b1) -> fp16.  jobs: 170m x 8n
    tc_gemm<E_RELU_F16><<<GPERS, 512, SMEM_GEMM>>>(
        xf, w1p, b1, nullptr, nullptr, nullptr, hff,
        1360, 8, 1, 4, 8, FFd, nullptr, nullptr);
    // ffn2 partials: p_off (kt=0), p_t1 (kt=1).  jobs: 170m x 2n x 2k, 8 super-chunks
    tc_gemm<E_PART><<<GPERS, 512, SMEM_GEMM>>>(
        hff, w2p, nullptr, nullptr, p_off, p_t1, nullptr,
        680, 2, 2, 8, 32, Dd, nullptr, nullptr);
    // out = LN(t2init + p0 + p1)
    ln_kernel<2><<<M, 256>>>(p_t2, g2, be2, (float*)d_out, nullptr, nullptr, nullptr, p_off, p_t1);
}

// round 14
// speedup vs baseline: 1.0602x; 1.0602x over previous
#include <cuda_runtime.h>
#include <cuda_fp16.h>
#include <math.h>
#include <stdint.h>

typedef __half hf;

// ---------------- problem constants ----------------
#define Bb 4
#define NTOK 5440
#define Mrows (Bb * NTOK)   // 21760
#define Dd 256
#define FFd 1024
#define GPERS 304

__device__ __constant__ int c_lvl_W[4]     = {64, 32, 16, 8};
__device__ __constant__ int c_lvl_start[4] = {0, 4096, 5120, 5376};

// ---------------- scratch (device globals) ----------------
__device__ hf    g_srcf[Mrows * Dd];
__device__ hf    g_qf  [Mrows * Dd];
__device__ hf    g_af  [Mrows * Dd];
__device__ hf    g_xf  [Mrows * Dd];
__device__ hf    g_hf  [Mrows * FFd];
__device__ hf    g_valhf[Mrows * Dd];
__device__ float g_off  [Mrows * Dd];     // off; then wout partial1; then ffn2 partial0
__device__ float g_attn [Mrows * 128];
__device__ float g_t1   [Mrows * Dd];     // wout partial0; then ffn2 partial1
__device__ float g_x    [Mrows * Dd];     // ffn2 partial2
__device__ float g_p3   [Mrows * Dd];     // ffn2 partial3
__device__ float g_t2   [Mrows * Dd];     // x + b2 (seeded by LN1)
// fp16 weights, blocked layout
__device__ hf g_wv[Dd*Dd];
__device__ hf g_wc[384*Dd];
__device__ hf g_wo[Dd*Dd];
__device__ hf g_w1[FFd*Dd];
__device__ hf g_w2[Dd*FFd];

// ---------------- blocked layout ----------------
__device__ __forceinline__ size_t blk_off(int row, int k, int K) {
    uint32_t o = (uint32_t)(row & 127) * 64 + (uint32_t)(k & 31) * 2;
    o = o ^ ((o >> 3) & 0x70);
    return ((size_t)((row >> 7) * (K >> 5) + (k >> 5)) << 13) + o;
}
#define SWZ(o) ((o) ^ (((o) >> 3) & 0x70))

// ---------------- PTX helpers ----------------
__device__ __forceinline__ uint32_t smem_u32(const void* p) {
    uint32_t a;
    asm("{ .reg .u64 t; cvta.to.shared.u64 t, %1; cvt.u32.u64 %0, t; }" : "=r"(a) : "l"(p));
    return a;
}
#define MBAR_INIT(addr, cnt) \
    asm volatile("mbarrier.init.shared.b64 [%0], %1;" :: "r"((uint32_t)(addr)), "r"((uint32_t)(cnt)) : "memory")
#define MBAR_ARRIVE(addr) \
    asm volatile("mbarrier.arrive.shared.b64 _, [%0];" :: "r"((uint32_t)(addr)) : "memory")
#define MBAR_EXPECT_TX(addr, tx) \
    asm volatile("mbarrier.arrive.expect_tx.shared.b64 _, [%0], %1;" :: "r"((uint32_t)(addr)), "r"((uint32_t)(tx)) : "memory")
#define BULK_G2S(dst, src, bytes, mbar) \
    asm volatile("cp.async.bulk.shared::cluster.global.mbarrier::complete_tx::bytes [%0], [%1], %2, [%3];" \
        :: "r"((uint32_t)(dst)), "l"(src), "r"((uint32_t)(bytes)), "r"((uint32_t)(mbar)) : "memory")
#define FENCE_ASYNC() asm volatile("fence.proxy.async.shared::cta;" ::: "memory")

#define MBAR_WAIT(addr, par) do { \
    uint32_t _m = (uint32_t)(addr); uint32_t _p = (uint32_t)(par); uint32_t _d; \
    asm volatile("{\n\t.reg .pred p;\n\t" \
        "mbarrier.try_wait.parity.acquire.cta.shared::cta.b64 p, [%1], %2;\n\t" \
        "selp.b32 %0, 1, 0, p;\n\t}" : "=r"(_d) : "r"(_m), "r"(_p) : "memory"); \
    if (!_d) { \
        asm volatile("{\n\t.reg .pred P1;\n\t" \
            "WL_%=:\n\t" \
            "mbarrier.try_wait.parity.acquire.cta.shared::cta.b64 P1, [%0], %1, 0x989680;\n\t" \
            "@P1 bra.uni WD_%=;\n\t" \
            "bra.uni WL_%=;\n\t" \
            "WD_%=:\n\t}" :: "r"(_m), "r"(_p) : "memory"); \
    } } while (0)

__device__ __forceinline__ void ldsm4(uint32_t* r, uint32_t a) {
    asm volatile("ldmatrix.sync.aligned.m8n8.x4.shared.b16 {%0,%1,%2,%3}, [%4];"
        : "=r"(r[0]), "=r"(r[1]), "=r"(r[2]), "=r"(r[3]) : "r"(a));
}
__device__ __forceinline__ void mma16816(float* d, const uint32_t* a, const uint32_t* b) {
    asm volatile("mma.sync.aligned.m16n8k16.row.col.f32.f16.f16.f32 "
        "{%0,%1,%2,%3}, {%4,%5,%6,%7}, {%8,%9}, {%0,%1,%2,%3};"
        : "+f"(d[0]), "+f"(d[1]), "+f"(d[2]), "+f"(d[3])
        : "r"(a[0]), "r"(a[1]), "r"(a[2]), "r"(a[3]), "r"(b[0]), "r"(b[1]));
}

__device__ __forceinline__ uint2 conv4(float4 v) {
    __half2 a = __floats2half2_rn(v.x, v.y);
    __half2 b = __floats2half2_rn(v.z, v.w);
    uint2 r; r.x = *(uint32_t*)&a; r.y = *(uint32_t*)&b;
    return r;
}

// ---------------- prep kernels ----------------
__global__ void src_q_conv(const float* __restrict__ src, const float* __restrict__ pos,
                           hf* __restrict__ sf, hf* __restrict__ qf) {
    int i = blockIdx.x * blockDim.x + threadIdx.x;
    int e = i * 4;
    int m = e >> 8, k = e & 255;
    size_t off = blk_off(m, k, 256);
    float4 s = ((const float4*)src)[i];
    float4 p = ((const float4*)pos)[i];
    *(uint2*)((char*)sf + off) = conv4(s);
    float4 q = make_float4(s.x + p.x, s.y + p.y, s.z + p.z, s.w + p.w);
    *(uint2*)((char*)qf + off) = conv4(q);
}

struct WConvArgs {
    const float* s[6];
    hf* h[6];
    int n4[6];
    int kshift[6];
    int rowoff[6];
};
__global__ void wconv_all(WConvArgs a) {
    int seg = blockIdx.y;
    int i = blockIdx.x * blockDim.x + threadIdx.x;
    if (i >= a.n4[seg]) return;
    int ks = a.kshift[seg];
    int K = 1 << ks;
    int e = i * 4;
    int m = (e >> ks) + a.rowoff[seg];
    int k = e & (K - 1);
    size_t off = blk_off(m, k, K);
    *(uint2*)((char*)a.h[seg] + off) = conv4(((const float4*)a.s[seg])[i]);
}

// ---------------- GEMM core config (R12-best: 256 thr, 8 warps 2x4, 64x32 tile) ----
#define NST 3
#define STG_B 32768
#define SMEM_GEMM (128 + NST * STG_B)

// ---------------- fused value+offattn GEMM ----------------
// jobs 0..339: value (m=job/2, n=job%2), A=srcf, B=wv, epi mask->valhf
// jobs 340..849: offattn (m=j/3, n=j%3), A=qf, B=wc, epi ->off/attn
__global__ __launch_bounds__(256, 2)
void gemm_qkv(const hf* __restrict__ As, const hf* __restrict__ Aq,
              const hf* __restrict__ Bv, const hf* __restrict__ Bc,
              const float* __restrict__ b_val, const float* __restrict__ b_off,
              const float* __restrict__ b_att,
              hf* __restrict__ valhf, float* __restrict__ offo, float* __restrict__ attno,
              const unsigned char* __restrict__ mask) {
    const int NJ = 850;
    extern __shared__ char sm[];
    const uint32_t smb = smem_u32(sm);
    const uint32_t fullb = smb, emptyb = smb + 48;
    const uint32_t stg0 = smb + 128;

    const int tid = threadIdx.x;
    const int wid = tid >> 5, lane = tid & 31;
    const int wm = wid & 1, wn = wid >> 1;
    const int g = lane >> 2, t4 = lane & 3;

    if (tid == 0) {
#pragma unroll
        for (int s = 0; s < NST; s++) {
            MBAR_INIT(fullb + s * 16, 1);
            MBAR_INIT(emptyb + s * 16, 8);
        }
        FENCE_ASYNC();
    }
    __syncthreads();

    const int G = gridDim.x;
    const int bid = blockIdx.x;
    const int njm = (bid < NJ) ? ((NJ - bid + G - 1) / G) : 0;
    const int T = njm * 4;

    auto decode = [&](int job, const char*& Ab, const char*& Bb2, int& seg, int& m, int& n) {
        if (job < 340) {
            seg = 0; m = job >> 1; n = job & 1;
            Ab = (const char*)As + ((size_t)m * 8 << 13);
            Bb2 = (const char*)Bv + ((size_t)n * 8 << 13);
        } else {
            int j = job - 340;
            seg = 1; m = j / 3; n = j - 3 * m;
            Ab = (const char*)Aq + ((size_t)m * 8 << 13);
            Bb2 = (const char*)Bc + ((size_t)n * 8 << 13);
        }
    };

    auto issue = [&](int t) {
        int jl = t >> 2, c = t & 3;
        int job = bid + jl * G;
        const char *Ab, *Bb2; int seg, m, n;
        decode(job, Ab, Bb2, seg, m, n);
        int s = t % NST;
        uint32_t dst = stg0 + s * STG_B;
        uint32_t mb = fullb + s * 16;
        MBAR_EXPECT_TX(mb, STG_B);
        BULK_G2S(dst,         Ab + ((size_t)c * 2 << 13), 16384, mb);
        BULK_G2S(dst + 16384, Bb2 + ((size_t)c * 2 << 13), 16384, mb);
    };

    if (tid == 0) {
        int pre = T < NST ? T : NST;
        for (int t = 0; t < pre; t++) issue(t);
    }

    float acc[4][4][4];
#pragma unroll
    for (int i = 0; i < 4; i++)
#pragma unroll
        for (int j = 0; j < 4; j++)
#pragma unroll
            for (int r = 0; r < 4; r++) acc[i][j][r] = 0.f;

    const uint32_t rA = (uint32_t)(lane & 15);
    const uint32_t qA = (uint32_t)(lane >> 4) * 16;
    const uint32_t rB = (uint32_t)(((lane >> 4) & 1) * 8 + (lane & 7));
    const uint32_t qB = (uint32_t)((lane >> 3) & 1) * 16;

    for (int t = 0; t < T; t++) {
        int jl = t >> 2, c = t & 3;
        const int s = t % NST;
        const int u = t / NST;
        MBAR_WAIT(fullb + s * 16, u & 1);

        const uint32_t st = stg0 + s * STG_B;
#pragma unroll
        for (int ks = 0; ks < 4; ks++) {
            const uint32_t blk = (uint32_t)(ks >> 1) * 8192;
            const uint32_t kb = (uint32_t)(ks & 1) * 32;
            uint32_t Af[4][4], Bf[2][4];
#pragma unroll
            for (int i = 0; i < 4; i++) {
                uint32_t o = (wm * 64 + i * 16 + rA) * 64 + qA + kb;
                o = SWZ(o);
                ldsm4(Af[i], st + blk + o);
            }
#pragma unroll
            for (int p = 0; p < 2; p++) {
                uint32_t o = (wn * 32 + p * 16 + rB) * 64 + qB + kb;
                o = SWZ(o);
                ldsm4(Bf[p], st + 16384 + blk + o);
            }
#pragma unroll
            for (int i = 0; i < 4; i++)
#pragma unroll
                for (int j = 0; j < 4; j++) {
                    const uint32_t* bp = &Bf[j >> 1][(j & 1) * 2];
                    mma16816(acc[i][j], Af[i], bp);
                }
        }
        __syncwarp();
        if (lane == 0) MBAR_ARRIVE(emptyb + s * 16);
        if (tid == 0 && t + NST < T) {
            MBAR_WAIT(emptyb + s * 16, u & 1);
            issue(t + NST);
        }

        if (c == 3) {
            int job = bid + jl * G;
            const char *Ab, *Bb2; int seg, mM, nN;
            decode(job, Ab, Bb2, seg, mM, nN);
            int bm = mM * 128, bn = nN * 128;
#pragma unroll
            for (int i = 0; i < 4; i++) {
                int row0 = bm + wm * 64 + i * 16 + g;
#pragma unroll
                for (int j = 0; j < 4; j++) {
                    int col = bn + wn * 32 + j * 8 + 2 * t4;
                    float b0, b1;
                    if (seg == 0) { b0 = b_val[col]; b1 = b_val[col + 1]; }
                    else if (bn == 256) { b0 = b_att[col - 256]; b1 = b_att[col - 255]; }
                    else { b0 = b_off[col]; b1 = b_off[col + 1]; }
#pragma unroll
                    for (int half = 0; half < 2; half++) {
                        int row = row0 + half * 8;
                        float v0 = acc[i][j][half * 2 + 0] + b0;
                        float v1 = acc[i][j][half * 2 + 1] + b1;
                        if (seg == 0) {
                            if (mask[row]) { v0 = 0.f; v1 = 0.f; }
                            __half2 pk = __floats2half2_rn(v0, v1);
                            *(uint32_t*)(valhf + (size_t)row * 256 + col) = *(uint32_t*)&pk;
                        } else if (bn == 256) {
                            *(float2*)(attno + (size_t)row * 128 + (col - 256)) = make_float2(v0, v1);
                        } else {
                            *(float2*)(offo + (size_t)row * 256 + col) = make_float2(v0, v1);
                        }
                    }
                }
            }
#pragma unroll
            for (int i = 0; i < 4; i++)
#pragma unroll
                for (int j = 0; j < 4; j++)
#pragma unroll
                    for (int r = 0; r < 4; r++) acc[i][j][r] = 0.f;
        }
    }
}

// ---------------- generic persistent GEMM (relu-f16 out or raw K-split partials) --
enum { E_RELU_F16 = 0, E_PART = 1 };

template <int EPI>
__global__ __launch_bounds__(256, 2)
void tc_gemm(const hf* __restrict__ A, const hf* __restrict__ B,
             const float* __restrict__ bias,
             float* __restrict__ pF0, float* __restrict__ pF1,
             float* __restrict__ pF2, float* __restrict__ pF3,
             hf* __restrict__ oF16,
             int NJ, int NTC, int KTC, int CHUNKS, int KCA, int N) {
    extern __shared__ char sm[];
    const uint32_t smb = smem_u32(sm);
    const uint32_t fullb = smb, emptyb = smb + 48;
    const uint32_t stg0 = smb + 128;

    const int tid = threadIdx.x;
    const int wid = tid >> 5, lane = tid & 31;
    const int wm = wid & 1, wn = wid >> 1;
    const int g = lane >> 2, t4 = lane & 3;

    if (tid == 0) {
#pragma unroll
        for (int s = 0; s < NST; s++) {
            MBAR_INIT(fullb + s * 16, 1);
            MBAR_INIT(emptyb + s * 16, 8);
        }
        FENCE_ASYNC();
    }
    __syncthreads();

    const int G = gridDim.x;
    const int bid = blockIdx.x;
    const int njm = (bid < NJ) ? ((NJ - bid + G - 1) / G) : 0;
    const int T = njm * CHUNKS;

    auto issue = [&](int t) {
        int jl = t / CHUNKS, c = t - jl * CHUNKS;
        int job = bid + jl * G;
        int n = job % NTC;
        int r = job / NTC;
        int kt = r % KTC;
        int m = r / KTC;
        int cg = kt * CHUNKS + c;
        int s = t % NST;
        uint32_t dst = stg0 + s * STG_B;
        uint32_t mb = fullb + s * 16;
        MBAR_EXPECT_TX(mb, STG_B);
        const char* a0 = (const char*)A + (((size_t)m * KCA + cg * 2) << 13);
        const char* b0 = (const char*)B + (((size_t)n * KCA + cg * 2) << 13);
        BULK_G2S(dst,         a0, 16384, mb);
        BULK_G2S(dst + 16384, b0, 16384, mb);
    };

    if (tid == 0) {
        int pre = T < NST ? T : NST;
        for (int t = 0; t < pre; t++) issue(t);
    }

    float acc[4][4][4];
#pragma unroll
    for (int i = 0; i < 4; i++)
#pragma unroll
        for (int j = 0; j < 4; j++)
#pragma unroll
            for (int r = 0; r < 4; r++) acc[i][j][r] = 0.f;

    const uint32_t rA = (uint32_t)(lane & 15);
    const uint32_t qA = (uint32_t)(lane >> 4) * 16;
    const uint32_t rB = (uint32_t)(((lane >> 4) & 1) * 8 + (lane & 7));
    const uint32_t qB = (uint32_t)((lane >> 3) & 1) * 16;

    int bm = 0, bn = 0, ktile = 0;

    for (int t = 0; t < T; t++) {
        int jl = t / CHUNKS, c = t - jl * CHUNKS;
        if (c == 0) {
            int job = bid + jl * G;
            int n = job % NTC;
            int r = job / NTC;
            ktile = r % KTC;
            int m = r / KTC;
            bm = m * 128;
            bn = n * 128;
        }
        const int s = t % NST;
        const int u = t / NST;
        MBAR_WAIT(fullb + s * 16, u & 1);

        const uint32_t st = stg0 + s * STG_B;
#pragma unroll
        for (int ks = 0; ks < 4; ks++) {
            const uint32_t blk = (uint32_t)(ks >> 1) * 8192;
            const uint32_t kb = (uint32_t)(ks & 1) * 32;
            uint32_t Af[4][4], Bf[2][4];
#pragma unroll
            for (int i = 0; i < 4; i++) {
                uint32_t o = (wm * 64 + i * 16 + rA) * 64 + qA + kb;
                o = SWZ(o);
                ldsm4(Af[i], st + blk + o);
            }
#pragma unroll
            for (int p = 0; p < 2; p++) {
                uint32_t o = (wn * 32 + p * 16 + rB) * 64 + qB + kb;
                o = SWZ(o);
                ldsm4(Bf[p], st + 16384 + blk + o);
            }
#pragma unroll
            for (int i = 0; i < 4; i++)
#pragma unroll
                for (int j = 0; j < 4; j++) {
                    const uint32_t* bp = &Bf[j >> 1][(j & 1) * 2];
                    mma16816(acc[i][j], Af[i], bp);
                }
        }
        __syncwarp();
        if (lane == 0) MBAR_ARRIVE(emptyb + s * 16);
        if (tid == 0 && t + NST < T) {
            MBAR_WAIT(emptyb + s * 16, u & 1);
            issue(t + NST);
        }

        if (c == CHUNKS - 1) {
            float* pbase = (ktile == 0) ? pF0 : (ktile == 1) ? pF1 : (ktile == 2) ? pF2 : pF3;
#pragma unroll
            for (int i = 0; i < 4; i++) {
                int row0 = bm + wm * 64 + i * 16 + g;
#pragma unroll
                for (int j = 0; j < 4; j++) {
                    int col = bn + wn * 32 + j * 8 + 2 * t4;
                    float b0 = (EPI == E_PART) ? 0.f : bias[col];
                    float b1 = (EPI == E_PART) ? 0.f : bias[col + 1];
#pragma unroll
                    for (int half = 0; half < 2; half++) {
                        int row = row0 + half * 8;
                        float v0 = acc[i][j][half * 2 + 0] + b0;
                        float v1 = acc[i][j][half * 2 + 1] + b1;
                        if (EPI == E_RELU_F16) {
                            v0 = fmaxf(v0, 0.f); v1 = fmaxf(v1, 0.f);
                            __half2 pk = __floats2half2_rn(v0, v1);
                            size_t off = blk_off(row, col, N);
                            *(uint32_t*)((char*)oF16 + off) = *(uint32_t*)&pk;
                        } else {
                            *(float2*)(pbase + (size_t)row * N + col) = make_float2(v0, v1);
                        }
                    }
                }
            }
#pragma unroll
            for (int i = 0; i < 4; i++)
#pragma unroll
                for (int j = 0; j < 4; j++)
#pragma unroll
                    for (int r = 0; r < 4; r++) acc[i][j][r] = 0.f;
        }
    }
}

// ---------------- msdeform sampling (fp16 value; R12 config) ----------------
__global__ __launch_bounds__(1024)
void sample_kernel(const float* __restrict__ ref, hf* __restrict__ af) {
    __shared__ int   s_off[32][32][4];
    __shared__ float s_w  [32][32][4];

    const int wid = threadIdx.x >> 5, lane = threadIdx.x & 31;
    const int tw = wid & 3;
    const int m = blockIdx.x * 8 + (wid >> 2);
    const int b = m / NTOK;
    const int hh = lane >> 4;
    const int head = (tw << 1) | hh;
    const int pt = lane & 15;

    float logit = g_attn[(size_t)m * 128 + head * 16 + pt];
    float mx = logit;
#pragma unroll
    for (int o = 8; o; o >>= 1) mx = fmaxf(mx, __shfl_xor_sync(0xffffffffu, mx, o, 16));
    float e = __expf(logit - mx);
    float sum = e;
#pragma unroll
    for (int o = 8; o; o >>= 1) sum += __shfl_xor_sync(0xffffffffu, sum, o, 16);
    float aw = e / sum;

    const int l = pt >> 2;
    const int Wl = c_lvl_W[l];
    float2 oxy = ((const float2*)g_off)[(size_t)m * 128 + head * 16 + pt];
    float2 rxy = ((const float2*)ref)[(size_t)m * 4 + l];
    float x = fmaf(rxy.x, (float)Wl, oxy.x) - 0.5f;
    float y = fmaf(rxy.y, (float)Wl, oxy.y) - 0.5f;
    float x0f = floorf(x), y0f = floorf(y);
    float fx = x - x0f, fy = y - y0f;
    int x0 = (int)x0f, y0 = (int)y0f;
    int x1 = x0 + 1, y1 = y0 + 1;
    bool vx0 = (x0 >= 0) & (x0 < Wl);
    bool vx1 = (x1 >= 0) & (x1 < Wl);
    bool vy0 = (y0 >= 0) & (y0 < Wl);
    bool vy1 = (y1 >= 0) & (y1 < Wl);
    int xc0 = min(max(x0, 0), Wl - 1), xc1 = min(max(x1, 0), Wl - 1);
    int yc0 = min(max(y0, 0), Wl - 1), yc1 = min(max(y1, 0), Wl - 1);
    float w00 = (vx0 & vy0) ? aw * (1.f - fx) * (1.f - fy) : 0.f;
    float w10 = (vx1 & vy0) ? aw * fx * (1.f - fy) : 0.f;
    float w01 = (vx0 & vy1) ? aw * (1.f - fx) * fy : 0.f;
    float w11 = (vx1 & vy1) ? aw * fx * fy : 0.f;
    int rowbase = b * NTOK + c_lvl_start[l];
    int hb = head * 64;
    s_off[wid][lane][0] = (rowbase + yc0 * Wl + xc0) * 512 + hb;
    s_off[wid][lane][1] = (rowbase + yc0 * Wl + xc1) * 512 + hb;
    s_off[wid][lane][2] = (rowbase + yc1 * Wl + xc0) * 512 + hb;
    s_off[wid][lane][3] = (rowbase + yc1 * Wl + xc1) * 512 + hb;
    s_w[wid][lane][0] = w00; s_w[wid][lane][1] = w10;
    s_w[wid][lane][2] = w01; s_w[wid][lane][3] = w11;
    __syncwarp();

    const int c2 = lane & 15;
    float accx = 0.f, accy = 0.f;
    const char* vb = (const char*)g_valhf + c2 * 4;
#pragma unroll
    for (int s = 0; s < 16; s++) {
        int slot = (hh << 4) | s;
        int4 io = *(const int4*)s_off[wid][slot];
        float4 wv = *(const float4*)s_w[wid][slot];
        __half2 v;
        float2 vf;
        v = *(const __half2*)(vb + io.x); vf = __half22float2(v);
        accx = fmaf(wv.x, vf.x, accx); accy = fmaf(wv.x, vf.y, accy);
        v = *(const __half2*)(vb + io.y); vf = __half22float2(v);
        accx = fmaf(wv.y, vf.x, accx); accy = fmaf(wv.y, vf.y, accy);
        v = *(const __half2*)(vb + io.z); vf = __half22float2(v);
        accx = fmaf(wv.z, vf.x, accx); accy = fmaf(wv.z, vf.y, accy);
        v = *(const __half2*)(vb + io.w); vf = __half22float2(v);
        accx = fmaf(wv.w, vf.x, accx); accy = fmaf(wv.w, vf.y, accy);
    }

    __half2 pk = __floats2half2_rn(accx, accy);
    int k0 = head * 32 + c2 * 2;
    size_t off = blk_off(m, k0, 256);
    *(uint32_t*)((char*)af + off) = *(uint32_t*)&pk;
}

// ---------------- LayerNorm 1: LN(src + p0 + p1 + b_out) -> xf (blocked) + t2init --
__global__ void ln1_kernel(const float* __restrict__ src,
                           const float* __restrict__ p0, const float* __restrict__ p1,
                           const float* __restrict__ badd,
                           const float* __restrict__ g, const float* __restrict__ be,
                           hf* __restrict__ oh,
                           float* __restrict__ t2i, const float* __restrict__ b2) {
    int m = blockIdx.x;
    int t = threadIdx.x;
    float v = src[(size_t)m * Dd + t] + p0[(size_t)m * Dd + t]
            + p1[(size_t)m * Dd + t] + badd[t];
    float s = v, sq = v * v;
#pragma unroll
    for (int o = 16; o; o >>= 1) {
        s += __shfl_xor_sync(0xffffffffu, s, o);
        sq += __shfl_xor_sync(0xffffffffu, sq, o);
    }
    __shared__ float ss[8], ssq[8];
    __shared__ float s_mean, s_rstd;
    if ((t & 31) == 0) { ss[t >> 5] = s; ssq[t >> 5] = sq; }
    __syncthreads();
    if (t == 0) {
        float ts = 0.f, tsq = 0.f;
#pragma unroll
        for (int i = 0; i < 8; i++) { ts += ss[i]; tsq += ssq[i]; }
        float mean = ts * (1.f / Dd);
        float var = tsq * (1.f / Dd) - mean * mean;
        s_mean = mean;
        s_rstd = rsqrtf(var + 1e-5f);
    }
    __syncthreads();
    float o = (v - s_mean) * s_rstd * g[t] + be[t];
    size_t off = blk_off(m, t, 256);
    *(hf*)((char*)oh + off) = __float2half_rn(o);
    t2i[(size_t)m * Dd + t] = o + b2[t];
}

// ---------------- LayerNorm 2: LN(t2init + p0+p1+p2+p3) -> out --------------------
__global__ void ln2_kernel(const float* __restrict__ in,
                           const float* __restrict__ p0, const float* __restrict__ p1,
                           const float* __restrict__ p2, const float* __restrict__ p3,
                           const float* __restrict__ g, const float* __restrict__ be,
                           float* __restrict__ out) {
    int m = blockIdx.x;
    int t = threadIdx.x;
    float v = in[(size_t)m * Dd + t] + p0[(size_t)m * Dd + t] + p1[(size_t)m * Dd + t]
            + p2[(size_t)m * Dd + t] + p3[(size_t)m * Dd + t];
    float s = v, sq = v * v;
#pragma unroll
    for (int o = 16; o; o >>= 1) {
        s += __shfl_xor_sync(0xffffffffu, s, o);
        sq += __shfl_xor_sync(0xffffffffu, sq, o);
    }
    __shared__ float ss[8], ssq[8];
    __shared__ float s_mean, s_rstd;
    if ((t & 31) == 0) { ss[t >> 5] = s; ssq[t >> 5] = sq; }
    __syncthreads();
    if (t == 0) {
        float ts = 0.f, tsq = 0.f;
#pragma unroll
        for (int i = 0; i < 8; i++) { ts += ss[i]; tsq += ssq[i]; }
        float mean = ts * (1.f / Dd);
        float var = tsq * (1.f / Dd) - mean * mean;
        s_mean = mean;
        s_rstd = rsqrtf(var + 1e-5f);
    }
    __syncthreads();
    out[(size_t)m * Dd + t] = (v - s_mean) * s_rstd * g[t] + be[t];
}

// ---------------- launch ----------------
extern "C" void kernel_launch(void* const* d_in, const int* in_sizes, int n_in,
                              void* d_out, int out_size) {
    const float* src   = (const float*)d_in[0];
    const float* pos   = (const float*)d_in[1];
    const float* ref   = (const float*)d_in[2];
    const float* w_val = (const float*)d_in[3];
    const float* b_val = (const float*)d_in[4];
    const float* w_off = (const float*)d_in[5];
    const float* b_off = (const float*)d_in[6];
    const float* w_att = (const float*)d_in[7];
    const float* b_att = (const float*)d_in[8];
    const float* w_out = (const float*)d_in[9];
    const float* b_out = (const float*)d_in[10];
    const float* g1    = (const float*)d_in[11];
    const float* be1   = (const float*)d_in[12];
    const float* w1    = (const float*)d_in[13];
    const float* b1    = (const float*)d_in[14];
    const float* w2    = (const float*)d_in[15];
    const float* b2    = (const float*)d_in[16];
    const float* g2    = (const float*)d_in[17];
    const float* be2   = (const float*)d_in[18];
    const unsigned char* mask = (const unsigned char*)d_in[21];

    hf *srcf, *qf, *af, *xf, *hff, *valhf;
    hf *wv, *wc, *wo, *w1p, *w2p;
    float *p_off, *p_attn, *p_t1, *p_x, *p_p3, *p_t2;
    cudaGetSymbolAddress((void**)&srcf, g_srcf);
    cudaGetSymbolAddress((void**)&qf, g_qf);
    cudaGetSymbolAddress((void**)&af, g_af);
    cudaGetSymbolAddress((void**)&xf, g_xf);
    cudaGetSymbolAddress((void**)&hff, g_hf);
    cudaGetSymbolAddress((void**)&valhf, g_valhf);
    cudaGetSymbolAddress((void**)&wv, g_wv);
    cudaGetSymbolAddress((void**)&wc, g_wc);
    cudaGetSymbolAddress((void**)&wo, g_wo);
    cudaGetSymbolAddress((void**)&w1p, g_w1);
    cudaGetSymbolAddress((void**)&w2p, g_w2);
    cudaGetSymbolAddress((void**)&p_off, g_off);
    cudaGetSymbolAddress((void**)&p_attn, g_attn);
    cudaGetSymbolAddress((void**)&p_t1, g_t1);
    cudaGetSymbolAddress((void**)&p_x, g_x);
    cudaGetSymbolAddress((void**)&p_p3, g_p3);
    cudaGetSymbolAddress((void**)&p_t2, g_t2);

    const int M = Mrows;
    cudaFuncSetAttribute(gemm_qkv,            cudaFuncAttributeMaxDynamicSharedMemorySize, SMEM_GEMM);
    cudaFuncSetAttribute(tc_gemm<E_RELU_F16>, cudaFuncAttributeMaxDynamicSharedMemorySize, SMEM_GEMM);
    cudaFuncSetAttribute(tc_gemm<E_PART>,     cudaFuncAttributeMaxDynamicSharedMemorySize, SMEM_GEMM);

    // prep
    src_q_conv<<<(M * Dd / 4) / 256, 256>>>(src, pos, srcf, qf);
    WConvArgs wa;
    wa.s[0] = w_val; wa.h[0] = wv;  wa.n4[0] = Dd * Dd / 4;  wa.kshift[0] = 8;  wa.rowoff[0] = 0;
    wa.s[1] = w_off; wa.h[1] = wc;  wa.n4[1] = Dd * Dd / 4;  wa.kshift[1] = 8;  wa.rowoff[1] = 0;
    wa.s[2] = w_att; wa.h[2] = wc;  wa.n4[2] = 128 * Dd / 4; wa.kshift[2] = 8;  wa.rowoff[2] = 256;
    wa.s[3] = w_out; wa.h[3] = wo;  wa.n4[3] = Dd * Dd / 4;  wa.kshift[3] = 8;  wa.rowoff[3] = 0;
    wa.s[4] = w1;    wa.h[4] = w1p; wa.n4[4] = FFd * Dd / 4; wa.kshift[4] = 8;  wa.rowoff[4] = 0;
    wa.s[5] = w2;    wa.h[5] = w2p; wa.n4[5] = Dd * FFd / 4; wa.kshift[5] = 10; wa.rowoff[5] = 0;
    wconv_all<<<dim3(256, 6), 256>>>(wa);

    // fused: value -> valhf ; [off;attn] -> p_off/p_attn.  850 pooled jobs.
    gemm_qkv<<<GPERS, 256, SMEM_GEMM>>>(srcf, qf, wv, wc, b_val, b_off, b_att,
                                        valhf, p_off, p_attn, mask);
    // msdeform -> blocked fp16 a
    sample_kernel<<<M / 8, 1024>>>(ref, af);
    // wout partials (K-split x2): p_t1 (kt0), p_off (kt1). 680 jobs of 2 super-chunks.
    tc_gemm<E_PART><<<GPERS, 256, SMEM_GEMM>>>(
        af, wo, nullptr, p_t1, p_off, nullptr, nullptr, nullptr,
        680, 2, 2, 2, 8, Dd);
    // x = LN(src + p0 + p1 + b_out); xf blocked; t2init = x + b2
    ln1_kernel<<<M, 256>>>(src, p_t1, p_off, b_out, g1, be1, xf, p_t2, b2);
    // h = relu(x @ W1^T + b1) -> fp16 blocked. 1360 jobs.
    tc_gemm<E_RELU_F16><<<GPERS, 256, SMEM_GEMM>>>(
        xf, w1p, b1, nullptr, nullptr, nullptr, nullptr, hff,
        1360, 8, 1, 4, 8, FFd);
    // ffn2 partials (K-split x4): p_off, p_t1, p_x, p_p3. 1360 jobs of 4 super-chunks.
    tc_gemm<E_PART><<<GPERS, 256, SMEM_GEMM>>>(
        hff, w2p, nullptr, p_off, p_t1, p_x, p_p3, nullptr,
        1360, 2, 4, 4, 32, Dd);
    // out = LN(t2init + 4 partials)
    ln2_kernel<<<M, 256>>>(p_t2, p_off, p_t1, p_x, p_p3, g2, be2, (float*)d_out);
}

// round 16
// speedup vs baseline: 1.1163x; 1.0530x over previous
#include <cuda_runtime.h>
#include <cuda_fp16.h>
#include <math.h>
#include <stdint.h>

typedef __half hf;

// ---------------- problem constants ----------------
#define Bb 4
#define NTOK 5440
#define Mrows (Bb * NTOK)   // 21760
#define Dd 256
#define FFd 1024
#define GPERS 304

__device__ __constant__ int c_lvl_W[4]     = {64, 32, 16, 8};
__device__ __constant__ int c_lvl_start[4] = {0, 4096, 5120, 5376};

// ---------------- scratch (device globals) ----------------
__device__ hf    g_srcf[Mrows * Dd];
__device__ hf    g_qf  [Mrows * Dd];
__device__ hf    g_af  [Mrows * Dd];
__device__ hf    g_xf  [Mrows * Dd];
__device__ hf    g_hf  [Mrows * FFd];
__device__ hf    g_valhf[Mrows * Dd];          // value fp16 row-major (sampler)
__device__ float g_off  [Mrows * Dd];          // offsets; later ffn2 partial 0
__device__ float g_attn [Mrows * 128];
__device__ float g_t1   [Mrows * Dd];          // pre-LN1; later ffn2 partial 1
__device__ float g_x    [Mrows * Dd];
__device__ float g_t2   [Mrows * Dd];          // x + b2 (seeded by LN1)
// fp16 weights, blocked layout
__device__ hf g_wv[Dd*Dd];
__device__ hf g_wc[384*Dd];
__device__ hf g_wo[Dd*Dd];
__device__ hf g_w1[FFd*Dd];
__device__ hf g_w2[Dd*FFd];

// ---------------- blocked layout ----------------
__device__ __forceinline__ size_t blk_off(int row, int k, int K) {
    uint32_t o = (uint32_t)(row & 127) * 64 + (uint32_t)(k & 31) * 2;
    o = o ^ ((o >> 3) & 0x70);
    return ((size_t)((row >> 7) * (K >> 5) + (k >> 5)) << 13) + o;
}
#define SWZ(o) ((o) ^ (((o) >> 3) & 0x70))

// ---------------- PTX helpers ----------------
__device__ __forceinline__ uint32_t smem_u32(const void* p) {
    uint32_t a;
    asm("{ .reg .u64 t; cvta.to.shared.u64 t, %1; cvt.u32.u64 %0, t; }" : "=r"(a) : "l"(p));
    return a;
}
#define MBAR_INIT(addr, cnt) \
    asm volatile("mbarrier.init.shared.b64 [%0], %1;" :: "r"((uint32_t)(addr)), "r"((uint32_t)(cnt)) : "memory")
#define MBAR_ARRIVE(addr) \
    asm volatile("mbarrier.arrive.shared.b64 _, [%0];" :: "r"((uint32_t)(addr)) : "memory")
#define MBAR_EXPECT_TX(addr, tx) \
    asm volatile("mbarrier.arrive.expect_tx.shared.b64 _, [%0], %1;" :: "r"((uint32_t)(addr)), "r"((uint32_t)(tx)) : "memory")
#define BULK_G2S(dst, src, bytes, mbar) \
    asm volatile("cp.async.bulk.shared::cluster.global.mbarrier::complete_tx::bytes [%0], [%1], %2, [%3];" \
        :: "r"((uint32_t)(dst)), "l"(src), "r"((uint32_t)(bytes)), "r"((uint32_t)(mbar)) : "memory")
#define FENCE_ASYNC() asm volatile("fence.proxy.async.shared::cta;" ::: "memory")

#define MBAR_WAIT(addr, par) do { \
    uint32_t _m = (uint32_t)(addr); uint32_t _p = (uint32_t)(par); uint32_t _d; \
    asm volatile("{\n\t.reg .pred p;\n\t" \
        "mbarrier.try_wait.parity.acquire.cta.shared::cta.b64 p, [%1], %2;\n\t" \
        "selp.b32 %0, 1, 0, p;\n\t}" : "=r"(_d) : "r"(_m), "r"(_p) : "memory"); \
    if (!_d) { \
        asm volatile("{\n\t.reg .pred P1;\n\t" \
            "WL_%=:\n\t" \
            "mbarrier.try_wait.parity.acquire.cta.shared::cta.b64 P1, [%0], %1, 0x989680;\n\t" \
            "@P1 bra.uni WD_%=;\n\t" \
            "bra.uni WL_%=;\n\t" \
            "WD_%=:\n\t}" :: "r"(_m), "r"(_p) : "memory"); \
    } } while (0)

__device__ __forceinline__ void ldsm4(uint32_t* r, uint32_t a) {
    asm volatile("ldmatrix.sync.aligned.m8n8.x4.shared.b16 {%0,%1,%2,%3}, [%4];"
        : "=r"(r[0]), "=r"(r[1]), "=r"(r[2]), "=r"(r[3]) : "r"(a));
}
__device__ __forceinline__ void mma16816(float* d, const uint32_t* a, const uint32_t* b) {
    asm volatile("mma.sync.aligned.m16n8k16.row.col.f32.f16.f16.f32 "
        "{%0,%1,%2,%3}, {%4,%5,%6,%7}, {%8,%9}, {%0,%1,%2,%3};"
        : "+f"(d[0]), "+f"(d[1]), "+f"(d[2]), "+f"(d[3])
        : "r"(a[0]), "r"(a[1]), "r"(a[2]), "r"(a[3]), "r"(b[0]), "r"(b[1]));
}

__device__ __forceinline__ uint2 conv4(float4 v) {
    __half2 a = __floats2half2_rn(v.x, v.y);
    __half2 b = __floats2half2_rn(v.z, v.w);
    uint2 r; r.x = *(uint32_t*)&a; r.y = *(uint32_t*)&b;
    return r;
}

// ---------------- prep kernels ----------------
__global__ void src_q_conv(const float* __restrict__ src, const float* __restrict__ pos,
                           hf* __restrict__ sf, hf* __restrict__ qf) {
    int i = blockIdx.x * blockDim.x + threadIdx.x;
    int e = i * 4;
    int m = e >> 8, k = e & 255;
    size_t off = blk_off(m, k, 256);
    float4 s = ((const float4*)src)[i];
    float4 p = ((const float4*)pos)[i];
    *(uint2*)((char*)sf + off) = conv4(s);
    float4 q = make_float4(s.x + p.x, s.y + p.y, s.z + p.z, s.w + p.w);
    *(uint2*)((char*)qf + off) = conv4(q);
}

struct WConvArgs {
    const float* s[6];
    hf* h[6];
    int n4[6];
    int kshift[6];
    int rowoff[6];
};
__global__ void wconv_all(WConvArgs a) {
    int seg = blockIdx.y;
    int i = blockIdx.x * blockDim.x + threadIdx.x;
    if (i >= a.n4[seg]) return;
    int ks = a.kshift[seg];
    int K = 1 << ks;
    int e = i * 4;
    int m = (e >> ks) + a.rowoff[seg];
    int k = e & (K - 1);
    size_t off = blk_off(m, k, K);
    *(uint2*)((char*)a.h[seg] + off) = conv4(((const float4*)a.s[seg])[i]);
}

// ---------------- persistent bulk-copy HMMA GEMM (R12 config) ----------------
#define NST 3
#define STG_B 32768
#define SMEM_GEMM (128 + NST * STG_B)
enum { E_MASK_F16 = 0, E_OFFATTN = 1, E_ADD = 2, E_RELU_F16 = 3, E_PART = 4 };

template <int EPI>
__global__ __launch_bounds__(256, 2)
void tc_gemm(const hf* __restrict__ A, const hf* __restrict__ B,
             const float* __restrict__ bias, const float* __restrict__ bias2,
             float* __restrict__ outF, float* __restrict__ outF2,
             hf* __restrict__ oF16,
             int NJ, int NTC, int KTC, int CHUNKS, int KCA, int N,
             const float* __restrict__ add, const unsigned char* __restrict__ mask) {
    extern __shared__ char sm[];
    const uint32_t smb = smem_u32(sm);
    const uint32_t fullb = smb, emptyb = smb + 48;
    const uint32_t stg0 = smb + 128;

    const int tid = threadIdx.x;
    const int wid = tid >> 5, lane = tid & 31;
    const int wm = wid & 1, wn = wid >> 1;
    const int g = lane >> 2, t4 = lane & 3;

    if (tid == 0) {
#pragma unroll
        for (int s = 0; s < NST; s++) {
            MBAR_INIT(fullb + s * 16, 1);
            MBAR_INIT(emptyb + s * 16, 8);
        }
        FENCE_ASYNC();
    }
    __syncthreads();

    const int G = gridDim.x;
    const int bid = blockIdx.x;
    const int njm = (bid < NJ) ? ((NJ - bid + G - 1) / G) : 0;
    const int T = njm * CHUNKS;

    auto issue = [&](int t) {
        int jl = t / CHUNKS, c = t - jl * CHUNKS;
        int job = bid + jl * G;
        int n = job % NTC;
        int r = job / NTC;
        int kt = (KTC == 2) ? (r & 1) : 0;
        int m = (KTC == 2) ? (r >> 1) : r;
        int cg = kt * CHUNKS + c;
        int s = t % NST;
        uint32_t dst = stg0 + s * STG_B;
        uint32_t mb = fullb + s * 16;
        MBAR_EXPECT_TX(mb, STG_B);
        const char* a0 = (const char*)A + (((size_t)m * KCA + cg * 2) << 13);
        const char* b0 = (const char*)B + (((size_t)n * KCA + cg * 2) << 13);
        BULK_G2S(dst,         a0, 16384, mb);
        BULK_G2S(dst + 16384, b0, 16384, mb);
    };

    if (tid == 0) {
        int pre = T < NST ? T : NST;
        for (int t = 0; t < pre; t++) issue(t);
    }

    float acc[4][4][4];
#pragma unroll
    for (int i = 0; i < 4; i++)
#pragma unroll
        for (int j = 0; j < 4; j++)
#pragma unroll
            for (int r = 0; r < 4; r++) acc[i][j][r] = 0.f;

    const uint32_t rA = (uint32_t)(lane & 15);
    const uint32_t qA = (uint32_t)(lane >> 4) * 16;
    const uint32_t rB = (uint32_t)(((lane >> 4) & 1) * 8 + (lane & 7));
    const uint32_t qB = (uint32_t)((lane >> 3) & 1) * 16;

    int bm = 0, bn = 0, ktile = 0;

    for (int t = 0; t < T; t++) {
        int jl = t / CHUNKS, c = t - jl * CHUNKS;
        if (c == 0) {
            int job = bid + jl * G;
            int n = job % NTC;
            int r = job / NTC;
            ktile = (KTC == 2) ? (r & 1) : 0;
            int m = (KTC == 2) ? (r >> 1) : r;
            bm = m * 128;
            bn = n * 128;
        }
        const int s = t % NST;
        const int u = t / NST;
        MBAR_WAIT(fullb + s * 16, u & 1);

        const uint32_t st = stg0 + s * STG_B;
#pragma unroll
        for (int ks = 0; ks < 4; ks++) {
            const uint32_t blk = (uint32_t)(ks >> 1) * 8192;
            const uint32_t kb = (uint32_t)(ks & 1) * 32;
            uint32_t Af[4][4], Bf[2][4];
#pragma unroll
            for (int i = 0; i < 4; i++) {
                uint32_t o = (wm * 64 + i * 16 + rA) * 64 + qA + kb;
                o = SWZ(o);
                ldsm4(Af[i], st + blk + o);
            }
#pragma unroll
            for (int p = 0; p < 2; p++) {
                uint32_t o = (wn * 32 + p * 16 + rB) * 64 + qB + kb;
                o = SWZ(o);
                ldsm4(Bf[p], st + 16384 + blk + o);
            }
#pragma unroll
            for (int i = 0; i < 4; i++)
#pragma unroll
                for (int j = 0; j < 4; j++) {
                    const uint32_t* bp = &Bf[j >> 1][(j & 1) * 2];
                    mma16816(acc[i][j], Af[i], bp);
                }
        }
        __syncwarp();
        if (lane == 0) MBAR_ARRIVE(emptyb + s * 16);
        if (tid == 0 && t + NST < T) {
            MBAR_WAIT(emptyb + s * 16, u & 1);
            issue(t + NST);
        }

        if (c == CHUNKS - 1) {
#pragma unroll
            for (int i = 0; i < 4; i++) {
                int row0 = bm + wm * 64 + i * 16 + g;
#pragma unroll
                for (int j = 0; j < 4; j++) {
                    int col = bn + wn * 32 + j * 8 + 2 * t4;
                    float b0, b1;
                    if (EPI == E_PART) { b0 = 0.f; b1 = 0.f; }
                    else if (EPI == E_OFFATTN && bn == 256) {
                        b0 = bias2[col - 256]; b1 = bias2[col - 255];
                    } else {
                        b0 = bias[col]; b1 = bias[col + 1];
                    }
#pragma unroll
                    for (int half = 0; half < 2; half++) {
                        int row = row0 + half * 8;
                        float v0 = acc[i][j][half * 2 + 0] + b0;
                        float v1 = acc[i][j][half * 2 + 1] + b1;
                        if (EPI == E_MASK_F16) {
                            if (mask[row]) { v0 = 0.f; v1 = 0.f; }
                            __half2 pk = __floats2half2_rn(v0, v1);
                            *(uint32_t*)(oF16 + (size_t)row * N + col) = *(uint32_t*)&pk;
                        } else if (EPI == E_OFFATTN) {
                            if (bn == 256)
                                *(float2*)(outF2 + (size_t)row * 128 + (col - 256)) = make_float2(v0, v1);
                            else
                                *(float2*)(outF + (size_t)row * 256 + col) = make_float2(v0, v1);
                        } else if (EPI == E_ADD) {
                            float2 r2 = *(const float2*)(add + (size_t)row * N + col);
                            *(float2*)(outF + (size_t)row * N + col) = make_float2(v0 + r2.x, v1 + r2.y);
                        } else if (EPI == E_RELU_F16) {
                            v0 = fmaxf(v0, 0.f); v1 = fmaxf(v1, 0.f);
                            __half2 pk = __floats2half2_rn(v0, v1);
                            size_t off = blk_off(row, col, N);
                            *(uint32_t*)((char*)oF16 + off) = *(uint32_t*)&pk;
                        } else if (EPI == E_PART) {
                            float* base = ktile ? outF2 : outF;
                            *(float2*)(base + (size_t)row * N + col) = make_float2(v0, v1);
                        }
                    }
                }
            }
#pragma unroll
            for (int i = 0; i < 4; i++)
#pragma unroll
                for (int j = 0; j < 4; j++)
#pragma unroll
                    for (int r = 0; r < 4; r++) acc[i][j][r] = 0.f;
        }
    }
}

// ---------------- msdeform sampling (fp16 value; HFMA2 inner loop) ----------------
// 1024 threads, 8 tokens/block (R12 shape). Phase 1 stores tap weights as
// replicated half2; phase 2 does 1 HFMA2 per tap, fp32 flush per point.
__global__ __launch_bounds__(1024)
void sample_kernel(const float* __restrict__ ref, hf* __restrict__ af) {
    __shared__ int      s_off[32][32][4];
    __shared__ uint32_t s_wh [32][32][4];   // half2-replicated tap weights

    const int wid = threadIdx.x >> 5, lane = threadIdx.x & 31;
    const int tw = wid & 3;
    const int m = blockIdx.x * 8 + (wid >> 2);
    const int b = m / NTOK;
    const int hh = lane >> 4;
    const int head = (tw << 1) | hh;
    const int pt = lane & 15;

    float logit = g_attn[(size_t)m * 128 + head * 16 + pt];
    float mx = logit;
#pragma unroll
    for (int o = 8; o; o >>= 1) mx = fmaxf(mx, __shfl_xor_sync(0xffffffffu, mx, o, 16));
    float e = __expf(logit - mx);
    float sum = e;
#pragma unroll
    for (int o = 8; o; o >>= 1) sum += __shfl_xor_sync(0xffffffffu, sum, o, 16);
    float aw = e / sum;

    const int l = pt >> 2;
    const int Wl = c_lvl_W[l];
    float2 oxy = ((const float2*)g_off)[(size_t)m * 128 + head * 16 + pt];
    float2 rxy = ((const float2*)ref)[(size_t)m * 4 + l];
    float x = fmaf(rxy.x, (float)Wl, oxy.x) - 0.5f;
    float y = fmaf(rxy.y, (float)Wl, oxy.y) - 0.5f;
    float x0f = floorf(x), y0f = floorf(y);
    float fx = x - x0f, fy = y - y0f;
    int x0 = (int)x0f, y0 = (int)y0f;
    int x1 = x0 + 1, y1 = y0 + 1;
    bool vx0 = (x0 >= 0) & (x0 < Wl);
    bool vx1 = (x1 >= 0) & (x1 < Wl);
    bool vy0 = (y0 >= 0) & (y0 < Wl);
    bool vy1 = (y1 >= 0) & (y1 < Wl);
    int xc0 = min(max(x0, 0), Wl - 1), xc1 = min(max(x1, 0), Wl - 1);
    int yc0 = min(max(y0, 0), Wl - 1), yc1 = min(max(y1, 0), Wl - 1);
    float w00 = (vx0 & vy0) ? aw * (1.f - fx) * (1.f - fy) : 0.f;
    float w10 = (vx1 & vy0) ? aw * fx * (1.f - fy) : 0.f;
    float w01 = (vx0 & vy1) ? aw * (1.f - fx) * fy : 0.f;
    float w11 = (vx1 & vy1) ? aw * fx * fy : 0.f;
    int rowbase = b * NTOK + c_lvl_start[l];
    int hb = head * 64;
    s_off[wid][lane][0] = (rowbase + yc0 * Wl + xc0) * 512 + hb;
    s_off[wid][lane][1] = (rowbase + yc0 * Wl + xc1) * 512 + hb;
    s_off[wid][lane][2] = (rowbase + yc1 * Wl + xc0) * 512 + hb;
    s_off[wid][lane][3] = (rowbase + yc1 * Wl + xc1) * 512 + hb;
    __half2 h00 = __float2half2_rn(w00), h10 = __float2half2_rn(w10);
    __half2 h01 = __float2half2_rn(w01), h11 = __float2half2_rn(w11);
    s_wh[wid][lane][0] = *(uint32_t*)&h00;
    s_wh[wid][lane][1] = *(uint32_t*)&h10;
    s_wh[wid][lane][2] = *(uint32_t*)&h01;
    s_wh[wid][lane][3] = *(uint32_t*)&h11;
    __syncwarp();

    const int c2 = lane & 15;
    float accx = 0.f, accy = 0.f;
    const char* vb = (const char*)g_valhf + c2 * 4;
    const __half2 hz = __float2half2_rn(0.f);
#pragma unroll
    for (int s = 0; s < 16; s++) {
        int slot = (hh << 4) | s;
        int4 io = *(const int4*)s_off[wid][slot];
        uint4 ww = *(const uint4*)s_wh[wid][slot];
        __half2 p = hz;
        p = __hfma2(*(const __half2*)(vb + io.x), *(__half2*)&ww.x, p);
        p = __hfma2(*(const __half2*)(vb + io.y), *(__half2*)&ww.y, p);
        p = __hfma2(*(const __half2*)(vb + io.z), *(__half2*)&ww.z, p);
        p = __hfma2(*(const __half2*)(vb + io.w), *(__half2*)&ww.w, p);
        float2 pf = __half22float2(p);
        accx += pf.x;
        accy += pf.y;
    }

    __half2 pk = __floats2half2_rn(accx, accy);
    int k0 = head * 32 + c2 * 2;
    size_t off = blk_off(m, k0, 256);
    *(uint32_t*)((char*)af + off) = *(uint32_t*)&pk;
}

// ---------------- LayerNorm over D=256 ----------------
// MODE 0: plain. MODE 1: LN1 (+ fp16 blocked out + t2init = o + b2).
// MODE 2: LN over (in + p0 + p1).
template <int MODE>
__global__ void ln_kernel(const float* __restrict__ in, const float* __restrict__ g,
                          const float* __restrict__ be, float* __restrict__ out,
                          hf* __restrict__ oh,
                          float* __restrict__ t2i, const float* __restrict__ b2,
                          const float* __restrict__ p0, const float* __restrict__ p1) {
    int m = blockIdx.x;
    int t = threadIdx.x;
    float v = in[(size_t)m * Dd + t];
    if (MODE == 2) v += p0[(size_t)m * Dd + t] + p1[(size_t)m * Dd + t];
    float s = v, sq = v * v;
#pragma unroll
    for (int o = 16; o; o >>= 1) {
        s += __shfl_xor_sync(0xffffffffu, s, o);
        sq += __shfl_xor_sync(0xffffffffu, sq, o);
    }
    __shared__ float ss[8], ssq[8];
    __shared__ float s_mean, s_rstd;
    if ((t & 31) == 0) { ss[t >> 5] = s; ssq[t >> 5] = sq; }
    __syncthreads();
    if (t == 0) {
        float ts = 0.f, tsq = 0.f;
#pragma unroll
        for (int i = 0; i < 8; i++) { ts += ss[i]; tsq += ssq[i]; }
        float mean = ts * (1.f / Dd);
        float var = tsq * (1.f / Dd) - mean * mean;
        s_mean = mean;
        s_rstd = rsqrtf(var + 1e-5f);
    }
    __syncthreads();
    float o = (v - s_mean) * s_rstd * g[t] + be[t];
    out[(size_t)m * Dd + t] = o;
    if (MODE == 1) {
        size_t off = blk_off(m, t, 256);
        *(hf*)((char*)oh + off) = __float2half_rn(o);
        t2i[(size_t)m * Dd + t] = o + b2[t];
    }
}

// ---------------- launch ----------------
extern "C" void kernel_launch(void* const* d_in, const int* in_sizes, int n_in,
                              void* d_out, int out_size) {
    const float* src   = (const float*)d_in[0];
    const float* pos   = (const float*)d_in[1];
    const float* ref   = (const float*)d_in[2];
    const float* w_val = (const float*)d_in[3];
    const float* b_val = (const float*)d_in[4];
    const float* w_off = (const float*)d_in[5];
    const float* b_off = (const float*)d_in[6];
    const float* w_att = (const float*)d_in[7];
    const float* b_att = (const float*)d_in[8];
    const float* w_out = (const float*)d_in[9];
    const float* b_out = (const float*)d_in[10];
    const float* g1    = (const float*)d_in[11];
    const float* be1   = (const float*)d_in[12];
    const float* w1    = (const float*)d_in[13];
    const float* b1    = (const float*)d_in[14];
    const float* w2    = (const float*)d_in[15];
    const float* b2    = (const float*)d_in[16];
    const float* g2    = (const float*)d_in[17];
    const float* be2   = (const float*)d_in[18];
    const unsigned char* mask = (const unsigned char*)d_in[21];

    hf *srcf, *qf, *af, *xf, *hff, *valhf;
    hf *wv, *wc, *wo, *w1p, *w2p;
    float *p_off, *p_attn, *p_t1, *p_x, *p_t2;
    cudaGetSymbolAddress((void**)&srcf, g_srcf);
    cudaGetSymbolAddress((void**)&qf, g_qf);
    cudaGetSymbolAddress((void**)&af, g_af);
    cudaGetSymbolAddress((void**)&xf, g_xf);
    cudaGetSymbolAddress((void**)&hff, g_hf);
    cudaGetSymbolAddress((void**)&valhf, g_valhf);
    cudaGetSymbolAddress((void**)&wv, g_wv);
    cudaGetSymbolAddress((void**)&wc, g_wc);
    cudaGetSymbolAddress((void**)&wo, g_wo);
    cudaGetSymbolAddress((void**)&w1p, g_w1);
    cudaGetSymbolAddress((void**)&w2p, g_w2);
    cudaGetSymbolAddress((void**)&p_off, g_off);
    cudaGetSymbolAddress((void**)&p_attn, g_attn);
    cudaGetSymbolAddress((void**)&p_t1, g_t1);
    cudaGetSymbolAddress((void**)&p_x, g_x);
    cudaGetSymbolAddress((void**)&p_t2, g_t2);

    const int M = Mrows;
    cudaFuncSetAttribute(tc_gemm<E_MASK_F16>, cudaFuncAttributeMaxDynamicSharedMemorySize, SMEM_GEMM);
    cudaFuncSetAttribute(tc_gemm<E_OFFATTN>,  cudaFuncAttributeMaxDynamicSharedMemorySize, SMEM_GEMM);
    cudaFuncSetAttribute(tc_gemm<E_ADD>,      cudaFuncAttributeMaxDynamicSharedMemorySize, SMEM_GEMM);
    cudaFuncSetAttribute(tc_gemm<E_RELU_F16>, cudaFuncAttributeMaxDynamicSharedMemorySize, SMEM_GEMM);
    cudaFuncSetAttribute(tc_gemm<E_PART>,     cudaFuncAttributeMaxDynamicSharedMemorySize, SMEM_GEMM);

    // prep
    src_q_conv<<<(M * Dd / 4) / 256, 256>>>(src, pos, srcf, qf);
    WConvArgs wa;
    wa.s[0] = w_val; wa.h[0] = wv;  wa.n4[0] = Dd * Dd / 4;  wa.kshift[0] = 8;  wa.rowoff[0] = 0;
    wa.s[1] = w_off; wa.h[1] = wc;  wa.n4[1] = Dd * Dd / 4;  wa.kshift[1] = 8;  wa.rowoff[1] = 0;
    wa.s[2] = w_att; wa.h[2] = wc;  wa.n4[2] = 128 * Dd / 4; wa.kshift[2] = 8;  wa.rowoff[2] = 256;
    wa.s[3] = w_out; wa.h[3] = wo;  wa.n4[3] = Dd * Dd / 4;  wa.kshift[3] = 8;  wa.rowoff[3] = 0;
    wa.s[4] = w1;    wa.h[4] = w1p; wa.n4[4] = FFd * Dd / 4; wa.kshift[4] = 8;  wa.rowoff[4] = 0;
    wa.s[5] = w2;    wa.h[5] = w2p; wa.n4[5] = Dd * FFd / 4; wa.kshift[5] = 10; wa.rowoff[5] = 0;
    wconv_all<<<dim3(256, 6), 256>>>(wa);

    // value = mask(src @ Wv^T + b) -> fp16.  jobs: 170m x 2n, 4 super-chunks
    tc_gemm<E_MASK_F16><<<GPERS, 256, SMEM_GEMM>>>(
        srcf, wv, b_val, nullptr, nullptr, nullptr, valhf,
        340, 2, 1, 4, 8, Dd, nullptr, mask);
    // [off ; attn] = q @ Wc^T + b.  jobs: 170m x 3n
    tc_gemm<E_OFFATTN><<<GPERS, 256, SMEM_GEMM>>>(
        qf, wc, b_off, b_att, p_off, p_attn, nullptr,
        510, 3, 1, 4, 8, 384, nullptr, nullptr);
    // msdeform -> blocked fp16 a   (8 tokens per 1024-thr block)
    sample_kernel<<<M / 8, 1024>>>(ref, af);
    // t1 = src + a @ Wo^T + b.  jobs: 170m x 2n
    tc_gemm<E_ADD><<<GPERS, 256, SMEM_GEMM>>>(
        af, wo, b_out, nullptr, p_t1, nullptr, nullptr,
        340, 2, 1, 4, 8, Dd, src, nullptr);
    // x = LN(t1); t2init = x + b2
    ln_kernel<1><<<M, 256>>>(p_t1, g1, be1, p_x, xf, p_t2, b2, nullptr, nullptr);
    // h = relu(x @ W1^T + b1) -> fp16.  jobs: 170m x 8n
    tc_gemm<E_RELU_F16><<<GPERS, 256, SMEM_GEMM>>>(
        xf, w1p, b1, nullptr, nullptr, nullptr, hff,
        1360, 8, 1, 4, 8, FFd, nullptr, nullptr);
    // ffn2 partials: p_off (kt=0), p_t1 (kt=1).  jobs: 170m x 2n x 2k, 8 super-chunks
    tc_gemm<E_PART><<<GPERS, 256, SMEM_GEMM>>>(
        hff, w2p, nullptr, nullptr, p_off, p_t1, nullptr,
        680, 2, 2, 8, 32, Dd, nullptr, nullptr);
    // out = LN(t2init + p0 + p1)
    ln_kernel<2><<<M, 256>>>(p_t2, g2, be2, (float*)d_out, nullptr, nullptr, nullptr, p_off, p_t1);
}

// round 17
// speedup vs baseline: 1.1428x; 1.0238x over previous
#include <cuda_runtime.h>
#include <cuda_fp16.h>
#include <math.h>
#include <stdint.h>

typedef __half hf;

// ---------------- problem constants ----------------
#define Bb 4
#define NTOK 5440
#define Mrows (Bb * NTOK)   // 21760
#define Dd 256
#define FFd 1024
#define GPERS 304

__device__ __constant__ int c_lvl_W[4]     = {64, 32, 16, 8};
__device__ __constant__ int c_lvl_start[4] = {0, 4096, 5120, 5376};

// ---------------- scratch (device globals) ----------------
__device__ hf    g_srcf[Mrows * Dd];
__device__ hf    g_qf  [Mrows * Dd];
__device__ hf    g_af  [Mrows * Dd];
__device__ hf    g_xf  [Mrows * Dd];
__device__ hf    g_hf  [Mrows * FFd];
__device__ hf    g_valhf[Mrows * Dd];          // value fp16 row-major (sampler)
__device__ float g_off  [Mrows * Dd];          // offsets; later ffn2 partial 0
__device__ float g_attn [Mrows * 128];
__device__ float g_t1   [Mrows * Dd];          // pre-LN1; later ffn2 partial 1
__device__ float g_x    [Mrows * Dd];
__device__ float g_t2   [Mrows * Dd];          // x + b2 (seeded by LN1)
// fp16 weights, blocked layout
__device__ hf g_wv[Dd*Dd];
__device__ hf g_wc[384*Dd];
__device__ hf g_wo[Dd*Dd];
__device__ hf g_w1[FFd*Dd];
__device__ hf g_w2[Dd*FFd];

// ---------------- blocked layout ----------------
__device__ __forceinline__ size_t blk_off(int row, int k, int K) {
    uint32_t o = (uint32_t)(row & 127) * 64 + (uint32_t)(k & 31) * 2;
    o = o ^ ((o >> 3) & 0x70);
    return ((size_t)((row >> 7) * (K >> 5) + (k >> 5)) << 13) + o;
}
#define SWZ(o) ((o) ^ (((o) >> 3) & 0x70))

// ---------------- PTX helpers ----------------
__device__ __forceinline__ uint32_t smem_u32(const void* p) {
    uint32_t a;
    asm("{ .reg .u64 t; cvta.to.shared.u64 t, %1; cvt.u32.u64 %0, t; }" : "=r"(a) : "l"(p));
    return a;
}
#define MBAR_INIT(addr, cnt) \
    asm volatile("mbarrier.init.shared.b64 [%0], %1;" :: "r"((uint32_t)(addr)), "r"((uint32_t)(cnt)) : "memory")
#define MBAR_ARRIVE(addr) \
    asm volatile("mbarrier.arrive.shared.b64 _, [%0];" :: "r"((uint32_t)(addr)) : "memory")
#define MBAR_EXPECT_TX(addr, tx) \
    asm volatile("mbarrier.arrive.expect_tx.shared.b64 _, [%0], %1;" :: "r"((uint32_t)(addr)), "r"((uint32_t)(tx)) : "memory")
#define BULK_G2S(dst, src, bytes, mbar) \
    asm volatile("cp.async.bulk.shared::cluster.global.mbarrier::complete_tx::bytes [%0], [%1], %2, [%3];" \
        :: "r"((uint32_t)(dst)), "l"(src), "r"((uint32_t)(bytes)), "r"((uint32_t)(mbar)) : "memory")
#define FENCE_ASYNC() asm volatile("fence.proxy.async.shared::cta;" ::: "memory")

#define MBAR_WAIT(addr, par) do { \
    uint32_t _m = (uint32_t)(addr); uint32_t _p = (uint32_t)(par); uint32_t _d; \
    asm volatile("{\n\t.reg .pred p;\n\t" \
        "mbarrier.try_wait.parity.acquire.cta.shared::cta.b64 p, [%1], %2;\n\t" \
        "selp.b32 %0, 1, 0, p;\n\t}" : "=r"(_d) : "r"(_m), "r"(_p) : "memory"); \
    if (!_d) { \
        asm volatile("{\n\t.reg .pred P1;\n\t" \
            "WL_%=:\n\t" \
            "mbarrier.try_wait.parity.acquire.cta.shared::cta.b64 P1, [%0], %1, 0x989680;\n\t" \
            "@P1 bra.uni WD_%=;\n\t" \
            "bra.uni WL_%=;\n\t" \
            "WD_%=:\n\t}" :: "r"(_m), "r"(_p) : "memory"); \
    } } while (0)

__device__ __forceinline__ void ldsm4(uint32_t* r, uint32_t a) {
    asm volatile("ldmatrix.sync.aligned.m8n8.x4.shared.b16 {%0,%1,%2,%3}, [%4];"
        : "=r"(r[0]), "=r"(r[1]), "=r"(r[2]), "=r"(r[3]) : "r"(a));
}
__device__ __forceinline__ void mma16816(float* d, const uint32_t* a, const uint32_t* b) {
    asm volatile("mma.sync.aligned.m16n8k16.row.col.f32.f16.f16.f32 "
        "{%0,%1,%2,%3}, {%4,%5,%6,%7}, {%8,%9}, {%0,%1,%2,%3};"
        : "+f"(d[0]), "+f"(d[1]), "+f"(d[2]), "+f"(d[3])
        : "r"(a[0]), "r"(a[1]), "r"(a[2]), "r"(a[3]), "r"(b[0]), "r"(b[1]));
}

__device__ __forceinline__ uint2 conv4(float4 v) {
    __half2 a = __floats2half2_rn(v.x, v.y);
    __half2 b = __floats2half2_rn(v.z, v.w);
    uint2 r; r.x = *(uint32_t*)&a; r.y = *(uint32_t*)&b;
    return r;
}

// ---------------- prep kernels ----------------
__global__ void src_q_conv(const float* __restrict__ src, const float* __restrict__ pos,
                           hf* __restrict__ sf, hf* __restrict__ qf) {
    int i = blockIdx.x * blockDim.x + threadIdx.x;
    int e = i * 4;
    int m = e >> 8, k = e & 255;
    size_t off = blk_off(m, k, 256);
    float4 s = ((const float4*)src)[i];
    float4 p = ((const float4*)pos)[i];
    *(uint2*)((char*)sf + off) = conv4(s);
    float4 q = make_float4(s.x + p.x, s.y + p.y, s.z + p.z, s.w + p.w);
    *(uint2*)((char*)qf + off) = conv4(q);
}

struct WConvArgs {
    const float* s[6];
    hf* h[6];
    int n4[6];
    int kshift[6];
    int rowoff[6];
};
__global__ void wconv_all(WConvArgs a) {
    int seg = blockIdx.y;
    int i = blockIdx.x * blockDim.x + threadIdx.x;
    if (i >= a.n4[seg]) return;
    int ks = a.kshift[seg];
    int K = 1 << ks;
    int e = i * 4;
    int m = (e >> ks) + a.rowoff[seg];
    int k = e & (K - 1);
    size_t off = blk_off(m, k, K);
    *(uint2*)((char*)a.h[seg] + off) = conv4(((const float4*)a.s[seg])[i]);
}

// ---------------- persistent bulk-copy HMMA GEMM (R12 config) ----------------
#define NST 3
#define STG_B 32768
#define SMEM_GEMM (128 + NST * STG_B)
enum { E_MASK_F16 = 0, E_OFFATTN = 1, E_ADD = 2, E_RELU_F16 = 3, E_PART = 4 };

template <int EPI>
__global__ __launch_bounds__(256, 2)
void tc_gemm(const hf* __restrict__ A, const hf* __restrict__ B,
             const float* __restrict__ bias, const float* __restrict__ bias2,
             float* __restrict__ outF, float* __restrict__ outF2,
             hf* __restrict__ oF16,
             int NJ, int NTC, int KTC, int CHUNKS, int KCA, int N,
             const float* __restrict__ add, const unsigned char* __restrict__ mask) {
    extern __shared__ char sm[];
    const uint32_t smb = smem_u32(sm);
    const uint32_t fullb = smb, emptyb = smb + 48;
    const uint32_t stg0 = smb + 128;

    const int tid = threadIdx.x;
    const int wid = tid >> 5, lane = tid & 31;
    const int wm = wid & 1, wn = wid >> 1;
    const int g = lane >> 2, t4 = lane & 3;

    if (tid == 0) {
#pragma unroll
        for (int s = 0; s < NST; s++) {
            MBAR_INIT(fullb + s * 16, 1);
            MBAR_INIT(emptyb + s * 16, 8);
        }
        FENCE_ASYNC();
    }
    __syncthreads();

    const int G = gridDim.x;
    const int bid = blockIdx.x;
    const int njm = (bid < NJ) ? ((NJ - bid + G - 1) / G) : 0;
    const int T = njm * CHUNKS;

    auto issue = [&](int t) {
        int jl = t / CHUNKS, c = t - jl * CHUNKS;
        int job = bid + jl * G;
        int n = job % NTC;
        int r = job / NTC;
        int kt = (KTC == 2) ? (r & 1) : 0;
        int m = (KTC == 2) ? (r >> 1) : r;
        int cg = kt * CHUNKS + c;
        int s = t % NST;
        uint32_t dst = stg0 + s * STG_B;
        uint32_t mb = fullb + s * 16;
        MBAR_EXPECT_TX(mb, STG_B);
        const char* a0 = (const char*)A + (((size_t)m * KCA + cg * 2) << 13);
        const char* b0 = (const char*)B + (((size_t)n * KCA + cg * 2) << 13);
        BULK_G2S(dst,         a0, 16384, mb);
        BULK_G2S(dst + 16384, b0, 16384, mb);
    };

    if (tid == 0) {
        int pre = T < NST ? T : NST;
        for (int t = 0; t < pre; t++) issue(t);
    }

    float acc[4][4][4];
#pragma unroll
    for (int i = 0; i < 4; i++)
#pragma unroll
        for (int j = 0; j < 4; j++)
#pragma unroll
            for (int r = 0; r < 4; r++) acc[i][j][r] = 0.f;

    const uint32_t rA = (uint32_t)(lane & 15);
    const uint32_t qA = (uint32_t)(lane >> 4) * 16;
    const uint32_t rB = (uint32_t)(((lane >> 4) & 1) * 8 + (lane & 7));
    const uint32_t qB = (uint32_t)((lane >> 3) & 1) * 16;

    int bm = 0, bn = 0, ktile = 0;

    for (int t = 0; t < T; t++) {
        int jl = t / CHUNKS, c = t - jl * CHUNKS;
        if (c == 0) {
            int job = bid + jl * G;
            int n = job % NTC;
            int r = job / NTC;
            ktile = (KTC == 2) ? (r & 1) : 0;
            int m = (KTC == 2) ? (r >> 1) : r;
            bm = m * 128;
            bn = n * 128;
        }
        const int s = t % NST;
        const int u = t / NST;
        MBAR_WAIT(fullb + s * 16, u & 1);

        const uint32_t st = stg0 + s * STG_B;
#pragma unroll
        for (int ks = 0; ks < 4; ks++) {
            const uint32_t blk = (uint32_t)(ks >> 1) * 8192;
            const uint32_t kb = (uint32_t)(ks & 1) * 32;
            uint32_t Af[4][4], Bf[2][4];
#pragma unroll
            for (int i = 0; i < 4; i++) {
                uint32_t o = (wm * 64 + i * 16 + rA) * 64 + qA + kb;
                o = SWZ(o);
                ldsm4(Af[i], st + blk + o);
            }
#pragma unroll
            for (int p = 0; p < 2; p++) {
                uint32_t o = (wn * 32 + p * 16 + rB) * 64 + qB + kb;
                o = SWZ(o);
                ldsm4(Bf[p], st + 16384 + blk + o);
            }
#pragma unroll
            for (int i = 0; i < 4; i++)
#pragma unroll
                for (int j = 0; j < 4; j++) {
                    const uint32_t* bp = &Bf[j >> 1][(j & 1) * 2];
                    mma16816(acc[i][j], Af[i], bp);
                }
        }
        __syncwarp();
        if (lane == 0) MBAR_ARRIVE(emptyb + s * 16);
        if (tid == 0 && t + NST < T) {
            MBAR_WAIT(emptyb + s * 16, u & 1);
            issue(t + NST);
        }

        if (c == CHUNKS - 1) {
#pragma unroll
            for (int i = 0; i < 4; i++) {
                int row0 = bm + wm * 64 + i * 16 + g;
#pragma unroll
                for (int j = 0; j < 4; j++) {
                    int col = bn + wn * 32 + j * 8 + 2 * t4;
                    float b0, b1;
                    if (EPI == E_PART) { b0 = 0.f; b1 = 0.f; }
                    else if (EPI == E_OFFATTN && bn == 256) {
                        b0 = bias2[col - 256]; b1 = bias2[col - 255];
                    } else {
                        b0 = bias[col]; b1 = bias[col + 1];
                    }
#pragma unroll
                    for (int half = 0; half < 2; half++) {
                        int row = row0 + half * 8;
                        float v0 = acc[i][j][half * 2 + 0] + b0;
                        float v1 = acc[i][j][half * 2 + 1] + b1;
                        if (EPI == E_MASK_F16) {
                            if (mask[row]) { v0 = 0.f; v1 = 0.f; }
                            __half2 pk = __floats2half2_rn(v0, v1);
                            *(uint32_t*)(oF16 + (size_t)row * N + col) = *(uint32_t*)&pk;
                        } else if (EPI == E_OFFATTN) {
                            if (bn == 256)
                                *(float2*)(outF2 + (size_t)row * 128 + (col - 256)) = make_float2(v0, v1);
                            else
                                *(float2*)(outF + (size_t)row * 256 + col) = make_float2(v0, v1);
                        } else if (EPI == E_ADD) {
                            float2 r2 = *(const float2*)(add + (size_t)row * N + col);
                            *(float2*)(outF + (size_t)row * N + col) = make_float2(v0 + r2.x, v1 + r2.y);
                        } else if (EPI == E_RELU_F16) {
                            v0 = fmaxf(v0, 0.f); v1 = fmaxf(v1, 0.f);
                            __half2 pk = __floats2half2_rn(v0, v1);
                            size_t off = blk_off(row, col, N);
                            *(uint32_t*)((char*)oF16 + off) = *(uint32_t*)&pk;
                        } else if (EPI == E_PART) {
                            float* base = ktile ? outF2 : outF;
                            *(float2*)(base + (size_t)row * N + col) = make_float2(v0, v1);
                        }
                    }
                }
            }
#pragma unroll
            for (int i = 0; i < 4; i++)
#pragma unroll
                for (int j = 0; j < 4; j++)
#pragma unroll
                    for (int r = 0; r < 4; r++) acc[i][j][r] = 0.f;
        }
    }
}

// ---------------- msdeform sampling v4 ----------------
// 16 tokens/block, 1024 threads, 64KB dynamic smem.
// Phase 1: each thread computes 2 points (same code, tokens t and t+8).
// Phase 2: thread = (token, head, channel-quad); uint2 (8B) gathers, 2-point
// batched loads for MLP, fp16 per-point accumulation, fp32 across points.
__global__ __launch_bounds__(1024)
void sample_kernel(const float* __restrict__ ref, hf* __restrict__ af) {
    extern __shared__ char ssm[];
    int*      s_off = (int*)ssm;                       // [16][8][16][4] = 32KB
    uint32_t* s_wh  = (uint32_t*)(ssm + 32768);        // [16][8][16][4] = 32KB

    const int tid = threadIdx.x;
    const int wid = tid >> 5, lane = tid & 31;
    const int m0 = blockIdx.x * 16;

    // ---- phase 1 ----
#pragma unroll
    for (int half = 0; half < 2; half++) {
        const int tok = (wid >> 2) + half * 8;
        const int m = m0 + tok;
        const int b = m / NTOK;
        const int hh = lane >> 4;
        const int head = ((wid & 3) << 1) | hh;
        const int pt = lane & 15;

        float logit = g_attn[(size_t)m * 128 + head * 16 + pt];
        float mx = logit;
#pragma unroll
        for (int o = 8; o; o >>= 1) mx = fmaxf(mx, __shfl_xor_sync(0xffffffffu, mx, o, 16));
        float e = __expf(logit - mx);
        float sum = e;
#pragma unroll
        for (int o = 8; o; o >>= 1) sum += __shfl_xor_sync(0xffffffffu, sum, o, 16);
        float aw = e / sum;

        const int l = pt >> 2;
        const int Wl = c_lvl_W[l];
        float2 oxy = ((const float2*)g_off)[(size_t)m * 128 + head * 16 + pt];
        float2 rxy = ((const float2*)ref)[(size_t)m * 4 + l];
        float x = fmaf(rxy.x, (float)Wl, oxy.x) - 0.5f;
        float y = fmaf(rxy.y, (float)Wl, oxy.y) - 0.5f;
        float x0f = floorf(x), y0f = floorf(y);
        float fx = x - x0f, fy = y - y0f;
        int x0 = (int)x0f, y0 = (int)y0f;
        int x1 = x0 + 1, y1 = y0 + 1;
        bool vx0 = (x0 >= 0) & (x0 < Wl);
        bool vx1 = (x1 >= 0) & (x1 < Wl);
        bool vy0 = (y0 >= 0) & (y0 < Wl);
        bool vy1 = (y1 >= 0) & (y1 < Wl);
        int xc0 = min(max(x0, 0), Wl - 1), xc1 = min(max(x1, 0), Wl - 1);
        int yc0 = min(max(y0, 0), Wl - 1), yc1 = min(max(y1, 0), Wl - 1);
        float w00 = (vx0 & vy0) ? aw * (1.f - fx) * (1.f - fy) : 0.f;
        float w10 = (vx1 & vy0) ? aw * fx * (1.f - fy) : 0.f;
        float w01 = (vx0 & vy1) ? aw * (1.f - fx) * fy : 0.f;
        float w11 = (vx1 & vy1) ? aw * fx * fy : 0.f;
        int rowbase = b * NTOK + c_lvl_start[l];
        int slot = ((tok * 8 + head) * 16 + pt) * 4;
        s_off[slot + 0] = (rowbase + yc0 * Wl + xc0) * 512;
        s_off[slot + 1] = (rowbase + yc0 * Wl + xc1) * 512;
        s_off[slot + 2] = (rowbase + yc1 * Wl + xc0) * 512;
        s_off[slot + 3] = (rowbase + yc1 * Wl + xc1) * 512;
        __half2 h00 = __float2half2_rn(w00), h10 = __float2half2_rn(w10);
        __half2 h01 = __float2half2_rn(w01), h11 = __float2half2_rn(w11);
        s_wh[slot + 0] = *(uint32_t*)&h00;
        s_wh[slot + 1] = *(uint32_t*)&h10;
        s_wh[slot + 2] = *(uint32_t*)&h01;
        s_wh[slot + 3] = *(uint32_t*)&h11;
    }
    __syncthreads();

    // ---- phase 2 ----
    const int tk = tid >> 6;            // 0..15
    const int h  = (tid >> 3) & 7;      // 0..7
    const int q  = tid & 7;             // 0..7
    const char* vb = (const char*)g_valhf + h * 64 + q * 8;
    const int base = (tk * 8 + h) * 16 * 4;

    float a0 = 0.f, a1 = 0.f, a2 = 0.f, a3 = 0.f;
    const __half2 hz = __float2half2_rn(0.f);
#pragma unroll
    for (int p = 0; p < 16; p += 2) {
        int4 io0 = *(const int4*)(s_off + base + p * 4);
        int4 io1 = *(const int4*)(s_off + base + p * 4 + 4);
        uint4 w0 = *(const uint4*)(s_wh + base + p * 4);
        uint4 w1 = *(const uint4*)(s_wh + base + p * 4 + 4);
        uint2 v00 = *(const uint2*)(vb + io0.x);
        uint2 v01 = *(const uint2*)(vb + io0.y);
        uint2 v02 = *(const uint2*)(vb + io0.z);
        uint2 v03 = *(const uint2*)(vb + io0.w);
        uint2 v10 = *(const uint2*)(vb + io1.x);
        uint2 v11 = *(const uint2*)(vb + io1.y);
        uint2 v12 = *(const uint2*)(vb + io1.z);
        uint2 v13 = *(const uint2*)(vb + io1.w);
        __half2 pA = hz, pB = hz, qA = hz, qB = hz;
        pA = __hfma2(*(__half2*)&v00.x, *(__half2*)&w0.x, pA);
        pB = __hfma2(*(__half2*)&v00.y, *(__half2*)&w0.x, pB);
        pA = __hfma2(*(__half2*)&v01.x, *(__half2*)&w0.y, pA);
        pB = __hfma2(*(__half2*)&v01.y, *(__half2*)&w0.y, pB);
        pA = __hfma2(*(__half2*)&v02.x, *(__half2*)&w0.z, pA);
        pB = __hfma2(*(__half2*)&v02.y, *(__half2*)&w0.z, pB);
        pA = __hfma2(*(__half2*)&v03.x, *(__half2*)&w0.w, pA);
        pB = __hfma2(*(__half2*)&v03.y, *(__half2*)&w0.w, pB);
        qA = __hfma2(*(__half2*)&v10.x, *(__half2*)&w1.x, qA);
        qB = __hfma2(*(__half2*)&v10.y, *(__half2*)&w1.x, qB);
        qA = __hfma2(*(__half2*)&v11.x, *(__half2*)&w1.y, qA);
        qB = __hfma2(*(__half2*)&v11.y, *(__half2*)&w1.y, qB);
        qA = __hfma2(*(__half2*)&v12.x, *(__half2*)&w1.z, qA);
        qB = __hfma2(*(__half2*)&v12.y, *(__half2*)&w1.z, qB);
        qA = __hfma2(*(__half2*)&v13.x, *(__half2*)&w1.w, qA);
        qB = __hfma2(*(__half2*)&v13.y, *(__half2*)&w1.w, qB);
        float2 fA = __half22float2(pA), fB = __half22float2(pB);
        float2 gA = __half22float2(qA), gB = __half22float2(qB);
        a0 += fA.x + gA.x;
        a1 += fA.y + gA.y;
        a2 += fB.x + gB.x;
        a3 += fB.y + gB.y;
    }

    __half2 o0 = __floats2half2_rn(a0, a1);
    __half2 o1 = __floats2half2_rn(a2, a3);
    int k0 = h * 32 + q * 4;
    size_t off = blk_off(m0 + tk, k0, 256);
    uint2 ov; ov.x = *(uint32_t*)&o0; ov.y = *(uint32_t*)&o1;
    *(uint2*)((char*)af + off) = ov;
}

// ---------------- LayerNorm over D=256 ----------------
// MODE 0: plain. MODE 1: LN1 (+ fp16 blocked out + t2init = o + b2).
// MODE 2: LN over (in + p0 + p1).
template <int MODE>
__global__ void ln_kernel(const float* __restrict__ in, const float* __restrict__ g,
                          const float* __restrict__ be, float* __restrict__ out,
                          hf* __restrict__ oh,
                          float* __restrict__ t2i, const float* __restrict__ b2,
                          const float* __restrict__ p0, const float* __restrict__ p1) {
    int m = blockIdx.x;
    int t = threadIdx.x;
    float v = in[(size_t)m * Dd + t];
    if (MODE == 2) v += p0[(size_t)m * Dd + t] + p1[(size_t)m * Dd + t];
    float s = v, sq = v * v;
#pragma unroll
    for (int o = 16; o; o >>= 1) {
        s += __shfl_xor_sync(0xffffffffu, s, o);
        sq += __shfl_xor_sync(0xffffffffu, sq, o);
    }
    __shared__ float ss[8], ssq[8];
    __shared__ float s_mean, s_rstd;
    if ((t & 31) == 0) { ss[t >> 5] = s; ssq[t >> 5] = sq; }
    __syncthreads();
    if (t == 0) {
        float ts = 0.f, tsq = 0.f;
#pragma unroll
        for (int i = 0; i < 8; i++) { ts += ss[i]; tsq += ssq[i]; }
        float mean = ts * (1.f / Dd);
        float var = tsq * (1.f / Dd) - mean * mean;
        s_mean = mean;
        s_rstd = rsqrtf(var + 1e-5f);
    }
    __syncthreads();
    float o = (v - s_mean) * s_rstd * g[t] + be[t];
    out[(size_t)m * Dd + t] = o;
    if (MODE == 1) {
        size_t off = blk_off(m, t, 256);
        *(hf*)((char*)oh + off) = __float2half_rn(o);
        t2i[(size_t)m * Dd + t] = o + b2[t];
    }
}

// ---------------- launch ----------------
extern "C" void kernel_launch(void* const* d_in, const int* in_sizes, int n_in,
                              void* d_out, int out_size) {
    const float* src   = (const float*)d_in[0];
    const float* pos   = (const float*)d_in[1];
    const float* ref   = (const float*)d_in[2];
    const float* w_val = (const float*)d_in[3];
    const float* b_val = (const float*)d_in[4];
    const float* w_off = (const float*)d_in[5];
    const float* b_off = (const float*)d_in[6];
    const float* w_att = (const float*)d_in[7];
    const float* b_att = (const float*)d_in[8];
    const float* w_out = (const float*)d_in[9];
    const float* b_out = (const float*)d_in[10];
    const float* g1    = (const float*)d_in[11];
    const float* be1   = (const float*)d_in[12];
    const float* w1    = (const float*)d_in[13];
    const float* b1    = (const float*)d_in[14];
    const float* w2    = (const float*)d_in[15];
    const float* b2    = (const float*)d_in[16];
    const float* g2    = (const float*)d_in[17];
    const float* be2   = (const float*)d_in[18];
    const unsigned char* mask = (const unsigned char*)d_in[21];

    hf *srcf, *qf, *af, *xf, *hff, *valhf;
    hf *wv, *wc, *wo, *w1p, *w2p;
    float *p_off, *p_attn, *p_t1, *p_x, *p_t2;
    cudaGetSymbolAddress((void**)&srcf, g_srcf);
    cudaGetSymbolAddress((void**)&qf, g_qf);
    cudaGetSymbolAddress((void**)&af, g_af);
    cudaGetSymbolAddress((void**)&xf, g_xf);
    cudaGetSymbolAddress((void**)&hff, g_hf);
    cudaGetSymbolAddress((void**)&valhf, g_valhf);
    cudaGetSymbolAddress((void**)&wv, g_wv);
    cudaGetSymbolAddress((void**)&wc, g_wc);
    cudaGetSymbolAddress((void**)&wo, g_wo);
    cudaGetSymbolAddress((void**)&w1p, g_w1);
    cudaGetSymbolAddress((void**)&w2p, g_w2);
    cudaGetSymbolAddress((void**)&p_off, g_off);
    cudaGetSymbolAddress((void**)&p_attn, g_attn);
    cudaGetSymbolAddress((void**)&p_t1, g_t1);
    cudaGetSymbolAddress((void**)&p_x, g_x);
    cudaGetSymbolAddress((void**)&p_t2, g_t2);

    const int M = Mrows;
    cudaFuncSetAttribute(tc_gemm<E_MASK_F16>, cudaFuncAttributeMaxDynamicSharedMemorySize, SMEM_GEMM);
    cudaFuncSetAttribute(tc_gemm<E_OFFATTN>,  cudaFuncAttributeMaxDynamicSharedMemorySize, SMEM_GEMM);
    cudaFuncSetAttribute(tc_gemm<E_ADD>,      cudaFuncAttributeMaxDynamicSharedMemorySize, SMEM_GEMM);
    cudaFuncSetAttribute(tc_gemm<E_RELU_F16>, cudaFuncAttributeMaxDynamicSharedMemorySize, SMEM_GEMM);
    cudaFuncSetAttribute(tc_gemm<E_PART>,     cudaFuncAttributeMaxDynamicSharedMemorySize, SMEM_GEMM);
    cudaFuncSetAttribute(sample_kernel,       cudaFuncAttributeMaxDynamicSharedMemorySize, 65536);

    // prep
    src_q_conv<<<(M * Dd / 4) / 256, 256>>>(src, pos, srcf, qf);
    WConvArgs wa;
    wa.s[0] = w_val; wa.h[0] = wv;  wa.n4[0] = Dd * Dd / 4;  wa.kshift[0] = 8;  wa.rowoff[0] = 0;
    wa.s[1] = w_off; wa.h[1] = wc;  wa.n4[1] = Dd * Dd / 4;  wa.kshift[1] = 8;  wa.rowoff[1] = 0;
    wa.s[2] = w_att; wa.h[2] = wc;  wa.n4[2] = 128 * Dd / 4; wa.kshift[2] = 8;  wa.rowoff[2] = 256;
    wa.s[3] = w_out; wa.h[3] = wo;  wa.n4[3] = Dd * Dd / 4;  wa.kshift[3] = 8;  wa.rowoff[3] = 0;
    wa.s[4] = w1;    wa.h[4] = w1p; wa.n4[4] = FFd * Dd / 4; wa.kshift[4] = 8;  wa.rowoff[4] = 0;
    wa.s[5] = w2;    wa.h[5] = w2p; wa.n4[5] = Dd * FFd / 4; wa.kshift[5] = 10; wa.rowoff[5] = 0;
    wconv_all<<<dim3(256, 6), 256>>>(wa);

    // value = mask(src @ Wv^T + b) -> fp16.  jobs: 170m x 2n, 4 super-chunks
    tc_gemm<E_MASK_F16><<<GPERS, 256, SMEM_GEMM>>>(
        srcf, wv, b_val, nullptr, nullptr, nullptr, valhf,
        340, 2, 1, 4, 8, Dd, nullptr, mask);
    // [off ; attn] = q @ Wc^T + b.  jobs: 170m x 3n
    tc_gemm<E_OFFATTN><<<GPERS, 256, SMEM_GEMM>>>(
        qf, wc, b_off, b_att, p_off, p_attn, nullptr,
        510, 3, 1, 4, 8, 384, nullptr, nullptr);
    // msdeform -> blocked fp16 a   (16 tokens per 1024-thr block, 64KB smem)
    sample_kernel<<<M / 16, 1024, 65536>>>(ref, af);
    // t1 = src + a @ Wo^T + b.  jobs: 170m x 2n
    tc_gemm<E_ADD><<<GPERS, 256, SMEM_GEMM>>>(
        af, wo, b_out, nullptr, p_t1, nullptr, nullptr,
        340, 2, 1, 4, 8, Dd, src, nullptr);
    // x = LN(t1); t2init = x + b2
    ln_kernel<1><<<M, 256>>>(p_t1, g1, be1, p_x, xf, p_t2, b2, nullptr, nullptr);
    // h = relu(x @ W1^T + b1) -> fp16.  jobs: 170m x 8n
    tc_gemm<E_RELU_F16><<<GPERS, 256, SMEM_GEMM>>>(
        xf, w1p, b1, nullptr, nullptr, nullptr, hff,
        1360, 8, 1, 4, 8, FFd, nullptr, nullptr);
    // ffn2 partials: p_off (kt=0), p_t1 (kt=1).  jobs: 170m x 2n x 2k, 8 super-chunks
    tc_gemm<E_PART><<<GPERS, 256, SMEM_GEMM>>>(
        hff, w2p, nullptr, nullptr, p_off, p_t1, nullptr,
        680, 2, 2, 8, 32, Dd, nullptr, nullptr);
    // out = LN(t2init + p0 + p1)
    ln_kernel<2><<<M, 256>>>(p_t2, g2, be2, (float*)d_out, nullptr, nullptr, nullptr, p_off, p_t1);
}